// round 4
// baseline (speedup 1.0000x reference)
#include <cuda_runtime.h>
#include <cuda_bf16.h>
#include <cstdint>
#include <math.h>

#define B_WIN   3136
#define NTOK    64
#define DIM     256
#define HEADS   8
#define NW      49
#define LBIAS   225
#define ATT_SCALE 0.17677669529663687f  // 1/sqrt(32)

// Scratch (device globals; alloc APIs forbidden)
__device__ uint2 g_q2 [25690112];  // [B_*H][64][16] hi/lo bf16x2 per d-pair
__device__ uint2 g_k2 [25690112];
__device__ float g_v  [51380224];  // [B_*H][64][32] fp32
__device__ uint2 g_ot2[25690112];  // [B_*64][128] ctx pre-split
__device__ uint2 g_wq [98304];     // qkv_w pre-split [768][128]
__device__ uint2 g_wp [32768];     // proj_w pre-split [256][128]
__device__ float g_ptab[LBIAS * HEADS];

// ---------------------------------------------------------------------------
__device__ __forceinline__ void split2(float x, float y, uint32_t& hi, uint32_t& lo) {
    __nv_bfloat162 h = __floats2bfloat162_rn(x, y);
    float hx = __low2float(h), hy = __high2float(h);
    __nv_bfloat162 l = __floats2bfloat162_rn(x - hx, y - hy);
    hi = *reinterpret_cast<uint32_t*>(&h);
    lo = *reinterpret_cast<uint32_t*>(&l);
}

__device__ __forceinline__ void mma_bf16(float* c, const uint32_t* a, uint32_t b0, uint32_t b1) {
    asm volatile(
        "mma.sync.aligned.m16n8k16.row.col.f32.bf16.bf16.f32 "
        "{%0,%1,%2,%3}, {%4,%5,%6,%7}, {%8,%9}, {%0,%1,%2,%3};\n"
        : "+f"(c[0]), "+f"(c[1]), "+f"(c[2]), "+f"(c[3])
        : "r"(a[0]), "r"(a[1]), "r"(a[2]), "r"(a[3]), "r"(b0), "r"(b1));
}

// ---------------------------------------------------------------------------
// Kernel 1: DynamicPosBias MLP -> g_ptab[225][8]  (fp32 exact)
// ---------------------------------------------------------------------------
__device__ __forceinline__ void lnrelu16(const float* p, float* t,
                                         const float* gm, const float* bt) {
    float m = 0.f;
#pragma unroll
    for (int j = 0; j < 16; j++) m += p[j];
    m *= (1.f / 16.f);
    float v = 0.f;
#pragma unroll
    for (int j = 0; j < 16; j++) { float d = p[j] - m; v += d * d; }
    v *= (1.f / 16.f);
    float is = rsqrtf(v + 1e-5f);
#pragma unroll
    for (int j = 0; j < 16; j++) {
        float u = (p[j] - m) * is * gm[j] + bt[j];
        t[j] = u > 0.f ? u : 0.f;
    }
}

__global__ void dpb_kernel(const float* __restrict__ biases,
                           const float* __restrict__ pw, const float* __restrict__ pb,
                           const float* __restrict__ g1, const float* __restrict__ b1,
                           const float* __restrict__ w1, const float* __restrict__ c1,
                           const float* __restrict__ g2, const float* __restrict__ b2,
                           const float* __restrict__ w2, const float* __restrict__ c2,
                           const float* __restrict__ g3, const float* __restrict__ b3,
                           const float* __restrict__ w3, const float* __restrict__ c3) {
    int r = threadIdx.x;
    if (r >= LBIAS) return;
    float p[16], t[16];
    float x0 = biases[2 * r], x1 = biases[2 * r + 1];
#pragma unroll
    for (int j = 0; j < 16; j++) p[j] = x0 * pw[2 * j] + x1 * pw[2 * j + 1] + pb[j];
    lnrelu16(p, t, g1, b1);
#pragma unroll
    for (int o = 0; o < 16; o++) {
        float s = c1[o];
#pragma unroll
        for (int j = 0; j < 16; j++) s += t[j] * w1[o * 16 + j];
        p[o] = s;
    }
    lnrelu16(p, t, g2, b2);
#pragma unroll
    for (int o = 0; o < 16; o++) {
        float s = c2[o];
#pragma unroll
        for (int j = 0; j < 16; j++) s += t[j] * w2[o * 16 + j];
        p[o] = s;
    }
    lnrelu16(p, t, g3, b3);
#pragma unroll
    for (int o = 0; o < 8; o++) {
        float s = c3[o];
#pragma unroll
        for (int j = 0; j < 16; j++) s += t[j] * w3[o * 16 + j];
        g_ptab[r * 8 + o] = s;
    }
}

// ---------------------------------------------------------------------------
// Kernel 1b: pre-split weights into packed hi/lo uint2 tables
// ---------------------------------------------------------------------------
__global__ void wsplit_kernel(const float* __restrict__ qw, const float* __restrict__ pw) {
    int i = blockIdx.x * blockDim.x + threadIdx.x;
    if (i < 98304) {
        float2 f = ((const float2*)qw)[i];
        split2(f.x, f.y, g_wq[i].x, g_wq[i].y);
    } else if (i < 98304 + 32768) {
        int j = i - 98304;
        float2 f = ((const float2*)pw)[j];
        split2(f.x, f.y, g_wp[j].x, g_wp[j].y);
    }
}

// ---------------------------------------------------------------------------
// Kernel 2/4: Y[M,NO] = A[M,256] @ W[NO,256]^T + bias ; BM=BN=128, BK=32.
// MODE 0: A = x (fp32, split in loader), B = g_wq; epilogue scatters q/k/v.
// MODE 1: A = g_ot2 (pre-split),         B = g_wp; epilogue -> Out.
// smem rows padded to 20 uint2 (stride 40 words % 32 == 8 -> conflict-free
// 64-bit quad fragment reads).
// ---------------------------------------------------------------------------
template <int MODE>
__global__ __launch_bounds__(256, 2) void gemm_kernel(const float* __restrict__ Ain,
                                                      const float* __restrict__ bias,
                                                      float* __restrict__ Out) {
    __shared__ uint2 A2[128][20];
    __shared__ uint2 B2[128][20];

    int bm = blockIdx.y, bn = blockIdx.x;
    int tid = threadIdx.x;
    int warp = tid >> 5, lane = tid & 31;
    int wm = warp >> 1, wn = warp & 1;
    int g = lane >> 2, tg = lane & 3;

    float acc[2][8][4];
#pragma unroll
    for (int a = 0; a < 2; a++)
#pragma unroll
        for (int b = 0; b < 8; b++)
#pragma unroll
            for (int c = 0; c < 4; c++) acc[a][b][c] = 0.f;

    const float* Af   = Ain + (size_t)bm * 128 * 256;                 // MODE 0
    const uint2* Ap   = g_ot2 + (size_t)bm * 128 * 128;               // MODE 1
    const uint2* Wb   = (MODE ? g_wp : g_wq) + (size_t)bn * 128 * 128;

    int r0 = tid >> 3;          // 0..31
    int cc = (tid & 7) * 4;     // fp32 col within 32-wide K tile
    int jj = cc >> 1;           // d-pair col: 0,2,..,14

    uint4 sa[4], sb[4];         // staged 16B chunks (2 d-pairs each)

    auto ldg_half = [&](int kb, int half) {
#pragma unroll
        for (int i = 0; i < 2; i++) {
            int idx = half * 2 + i;
            int r = r0 + idx * 32;
            if (MODE == 0)
                sa[idx] = *(const uint4*)(Af + (size_t)r * 256 + kb * 32 + cc);
            else
                sa[idx] = *(const uint4*)(Ap + (size_t)r * 128 + kb * 16 + jj);
            sb[idx] = *(const uint4*)(Wb + (size_t)r * 128 + kb * 16 + jj);
        }
    };
    auto sts_all = [&]() {
#pragma unroll
        for (int idx = 0; idx < 4; idx++) {
            int r = r0 + idx * 32;
            if (MODE == 0) {
                float4 f = *reinterpret_cast<float4*>(&sa[idx]);
                split2(f.x, f.y, A2[r][jj].x, A2[r][jj].y);
                split2(f.z, f.w, A2[r][jj + 1].x, A2[r][jj + 1].y);
            } else {
                A2[r][jj]     = make_uint2(sa[idx].x, sa[idx].y);
                A2[r][jj + 1] = make_uint2(sa[idx].z, sa[idx].w);
            }
            B2[r][jj]     = make_uint2(sb[idx].x, sb[idx].y);
            B2[r][jj + 1] = make_uint2(sb[idx].z, sb[idx].w);
        }
    };

    int mr = wm * 32;
    ldg_half(0, 0); ldg_half(0, 1);

    for (int kb = 0; kb < 8; kb++) {
        sts_all();
        __syncthreads();
        if (kb < 7) ldg_half(kb + 1, 0);
#pragma unroll
        for (int ks = 0; ks < 2; ks++) {
            int j0 = ks * 8;
            uint32_t ah0[4], al0[4], ah1[4], al1[4];
            {
                uint2 t;
                t = A2[mr + g][j0 + tg];          ah0[0] = t.x; al0[0] = t.y;
                t = A2[mr + g + 8][j0 + tg];      ah0[1] = t.x; al0[1] = t.y;
                t = A2[mr + g][j0 + tg + 4];      ah0[2] = t.x; al0[2] = t.y;
                t = A2[mr + g + 8][j0 + tg + 4];  ah0[3] = t.x; al0[3] = t.y;
                t = A2[mr + 16 + g][j0 + tg];         ah1[0] = t.x; al1[0] = t.y;
                t = A2[mr + 16 + g + 8][j0 + tg];     ah1[1] = t.x; al1[1] = t.y;
                t = A2[mr + 16 + g][j0 + tg + 4];     ah1[2] = t.x; al1[2] = t.y;
                t = A2[mr + 16 + g + 8][j0 + tg + 4]; ah1[3] = t.x; al1[3] = t.y;
            }
#pragma unroll
            for (int nfp = 0; nfp < 4; nfp++) {
                int nf0 = 2 * nfp, nf1 = nf0 + 1;
                int nA = wn * 64 + nf0 * 8 + g;
                uint2 c0 = B2[nA][j0 + tg],     c1 = B2[nA][j0 + tg + 4];
                uint2 d0 = B2[nA + 8][j0 + tg], d1 = B2[nA + 8][j0 + tg + 4];
                // term hi*hi (dep distance 4)
                mma_bf16(acc[0][nf0], ah0, c0.x, c1.x);
                mma_bf16(acc[1][nf0], ah1, c0.x, c1.x);
                mma_bf16(acc[0][nf1], ah0, d0.x, d1.x);
                mma_bf16(acc[1][nf1], ah1, d0.x, d1.x);
                // term hi*lo
                mma_bf16(acc[0][nf0], ah0, c0.y, c1.y);
                mma_bf16(acc[1][nf0], ah1, c0.y, c1.y);
                mma_bf16(acc[0][nf1], ah0, d0.y, d1.y);
                mma_bf16(acc[1][nf1], ah1, d0.y, d1.y);
                // term lo*hi
                mma_bf16(acc[0][nf0], al0, c0.x, c1.x);
                mma_bf16(acc[1][nf0], al1, c0.x, c1.x);
                mma_bf16(acc[0][nf1], al0, d0.x, d1.x);
                mma_bf16(acc[1][nf1], al1, d0.x, d1.x);
            }
            if (ks == 0 && kb < 7) ldg_half(kb + 1, 1);
        }
        __syncthreads();
    }

    int obase = bn * 128 + wn * 64;
#pragma unroll
    for (int nf = 0; nf < 8; nf++) {
        int o = obase + nf * 8 + 2 * tg;
        float bb0 = bias[o], bb1 = bias[o + 1];
#pragma unroll
        for (int mf = 0; mf < 2; mf++) {
#pragma unroll
            for (int r2 = 0; r2 < 2; r2++) {
                int m = bm * 128 + wm * 32 + mf * 16 + g + r2 * 8;
                float v0 = acc[mf][nf][r2 * 2] + bb0;
                float v1 = acc[mf][nf][r2 * 2 + 1] + bb1;
                if (MODE == 1) {
                    *(float2*)(Out + (size_t)m * 256 + o) = make_float2(v0, v1);
                } else {
                    int s = o >> 8, hh = (o >> 5) & 7, d = o & 31;
                    int bw = m >> 6, n = m & 63;
                    size_t di = ((size_t)(bw * 8 + hh) * 64 + n) * 16 + (d >> 1);
                    if (s == 0) {
                        uint2 u; split2(v0 * ATT_SCALE, v1 * ATT_SCALE, u.x, u.y);
                        g_q2[di] = u;
                    } else if (s == 1) {
                        uint2 u; split2(v0, v1, u.x, u.y);
                        g_k2[di] = u;
                    } else {
                        *(float2*)(g_v + (di << 1)) = make_float2(v0, v1);
                    }
                }
            }
        }
    }
}

// ---------------------------------------------------------------------------
// Kernel 3: attention per (window b, head h). 4 warps, 16 query rows each.
// q/k arrive pre-split; v split in loader; probs pre-split to p2; ctx -> g_ot2.
// ---------------------------------------------------------------------------
__global__ __launch_bounds__(128) void attn_kernel(const float* __restrict__ mask,
                                                   const int* __restrict__ rel_idx) {
    __shared__ uint2 q2s[64][20];
    __shared__ uint2 k2s[64][20];
    __shared__ uint2 vt2[32][36];   // V^T: [d][token-pair], stride 72 words % 32 == 8
    __shared__ uint2 p2 [64][36];   // probs

    int b = blockIdx.x, h = blockIdx.y;
    int tid = threadIdx.x;
    int warp = tid >> 5, lane = tid & 31;
    int g = lane >> 2, tg = lane & 3;

    const uint2* qg = g_q2 + (size_t)(b * 8 + h) * 1024;
    const uint2* kg = g_k2 + (size_t)(b * 8 + h) * 1024;
    const float* vg = g_v  + (size_t)(b * 8 + h) * 2048;

    for (int it = tid; it < 1024; it += 128) {
        int t = it >> 4, j = it & 15;
        q2s[t][j] = qg[it];
        k2s[t][j] = kg[it];
    }
    for (int it = tid; it < 1024; it += 128) {
        int d = it & 31, j = it >> 5;
        uint2 u;
        split2(vg[(2 * j) * 32 + d], vg[(2 * j + 1) * 32 + d], u.x, u.y);
        vt2[d][j] = u;
    }
    __syncthreads();

    // logits = q @ k^T  (q pre-scaled)
    float acc[8][4];
#pragma unroll
    for (int a = 0; a < 8; a++)
#pragma unroll
        for (int c = 0; c < 4; c++) acc[a][c] = 0.f;

    int mr = warp * 16;
#pragma unroll
    for (int ks = 0; ks < 2; ks++) {
        int j0 = ks * 8;
        uint32_t ah[4], al[4];
        {
            uint2 t;
            t = q2s[mr + g][j0 + tg];          ah[0] = t.x; al[0] = t.y;
            t = q2s[mr + g + 8][j0 + tg];      ah[1] = t.x; al[1] = t.y;
            t = q2s[mr + g][j0 + tg + 4];      ah[2] = t.x; al[2] = t.y;
            t = q2s[mr + g + 8][j0 + tg + 4];  ah[3] = t.x; al[3] = t.y;
        }
#pragma unroll
        for (int nfp = 0; nfp < 4; nfp++) {
            int nf0 = 2 * nfp, nf1 = nf0 + 1;
            int n0 = nf0 * 8 + g;
            uint2 c0 = k2s[n0][j0 + tg],     c1 = k2s[n0][j0 + tg + 4];
            uint2 d0 = k2s[n0 + 8][j0 + tg], d1 = k2s[n0 + 8][j0 + tg + 4];
            mma_bf16(acc[nf0], ah, c0.x, c1.x);
            mma_bf16(acc[nf1], ah, d0.x, d1.x);
            mma_bf16(acc[nf0], ah, c0.y, c1.y);
            mma_bf16(acc[nf1], ah, d0.y, d1.y);
            mma_bf16(acc[nf0], al, c0.x, c1.x);
            mma_bf16(acc[nf1], al, d0.x, d1.x);
        }
    }

    // bias gather + mask
    int wb = b % NW;
    const float* mrow = mask + (size_t)wb * 4096;
    int r0 = mr + g, r1 = r0 + 8;
#pragma unroll
    for (int nf = 0; nf < 8; nf++) {
        int n0 = nf * 8 + 2 * tg;
        acc[nf][0] += g_ptab[rel_idx[r0 * 64 + n0] * 8 + h]     + mrow[r0 * 64 + n0];
        acc[nf][1] += g_ptab[rel_idx[r0 * 64 + n0 + 1] * 8 + h] + mrow[r0 * 64 + n0 + 1];
        acc[nf][2] += g_ptab[rel_idx[r1 * 64 + n0] * 8 + h]     + mrow[r1 * 64 + n0];
        acc[nf][3] += g_ptab[rel_idx[r1 * 64 + n0 + 1] * 8 + h] + mrow[r1 * 64 + n0 + 1];
    }

    // softmax across the quad (rows r0, r1)
    float m0 = -1e30f, m1 = -1e30f;
#pragma unroll
    for (int nf = 0; nf < 8; nf++) {
        m0 = fmaxf(m0, fmaxf(acc[nf][0], acc[nf][1]));
        m1 = fmaxf(m1, fmaxf(acc[nf][2], acc[nf][3]));
    }
    m0 = fmaxf(m0, __shfl_xor_sync(0xffffffffu, m0, 1));
    m0 = fmaxf(m0, __shfl_xor_sync(0xffffffffu, m0, 2));
    m1 = fmaxf(m1, __shfl_xor_sync(0xffffffffu, m1, 1));
    m1 = fmaxf(m1, __shfl_xor_sync(0xffffffffu, m1, 2));

    float s0 = 0.f, s1 = 0.f;
#pragma unroll
    for (int nf = 0; nf < 8; nf++) {
        acc[nf][0] = __expf(acc[nf][0] - m0); s0 += acc[nf][0];
        acc[nf][1] = __expf(acc[nf][1] - m0); s0 += acc[nf][1];
        acc[nf][2] = __expf(acc[nf][2] - m1); s1 += acc[nf][2];
        acc[nf][3] = __expf(acc[nf][3] - m1); s1 += acc[nf][3];
    }
    s0 += __shfl_xor_sync(0xffffffffu, s0, 1);
    s0 += __shfl_xor_sync(0xffffffffu, s0, 2);
    s1 += __shfl_xor_sync(0xffffffffu, s1, 1);
    s1 += __shfl_xor_sync(0xffffffffu, s1, 2);
    float i0 = 1.f / s0, i1 = 1.f / s1;

#pragma unroll
    for (int nf = 0; nf < 8; nf++) {
        uint2 u;
        split2(acc[nf][0] * i0, acc[nf][1] * i0, u.x, u.y); p2[r0][nf * 4 + tg] = u;
        split2(acc[nf][2] * i1, acc[nf][3] * i1, u.x, u.y); p2[r1][nf * 4 + tg] = u;
    }
    __syncwarp();

    // out = P @ V
    float oacc[4][4];
#pragma unroll
    for (int a = 0; a < 4; a++)
#pragma unroll
        for (int c = 0; c < 4; c++) oacc[a][c] = 0.f;

#pragma unroll
    for (int ks = 0; ks < 4; ks++) {
        int j0 = ks * 8;
        uint32_t ah[4], al[4];
        {
            uint2 t;
            t = p2[mr + g][j0 + tg];          ah[0] = t.x; al[0] = t.y;
            t = p2[mr + g + 8][j0 + tg];      ah[1] = t.x; al[1] = t.y;
            t = p2[mr + g][j0 + tg + 4];      ah[2] = t.x; al[2] = t.y;
            t = p2[mr + g + 8][j0 + tg + 4];  ah[3] = t.x; al[3] = t.y;
        }
#pragma unroll
        for (int nfp = 0; nfp < 2; nfp++) {
            int nf0 = 2 * nfp, nf1 = nf0 + 1;
            int n0 = nf0 * 8 + g;
            uint2 c0 = vt2[n0][j0 + tg],     c1 = vt2[n0][j0 + tg + 4];
            uint2 d0 = vt2[n0 + 8][j0 + tg], d1 = vt2[n0 + 8][j0 + tg + 4];
            mma_bf16(oacc[nf0], ah, c0.x, c1.x);
            mma_bf16(oacc[nf1], ah, d0.x, d1.x);
            mma_bf16(oacc[nf0], ah, c0.y, c1.y);
            mma_bf16(oacc[nf1], ah, d0.y, d1.y);
            mma_bf16(oacc[nf0], al, c0.x, c1.x);
            mma_bf16(oacc[nf1], al, d0.x, d1.x);
        }
    }

    // ctx -> g_ot2[(b*64+n)][h*16 + dpair]  (pre-split for proj GEMM)
#pragma unroll
    for (int nf = 0; nf < 4; nf++) {
        int dp = h * 16 + nf * 4 + tg;
        uint2 u;
        split2(oacc[nf][0], oacc[nf][1], u.x, u.y);
        g_ot2[(size_t)(b * 64 + r0) * 128 + dp] = u;
        split2(oacc[nf][2], oacc[nf][3], u.x, u.y);
        g_ot2[(size_t)(b * 64 + r1) * 128 + dp] = u;
    }
}

// ---------------------------------------------------------------------------
extern "C" void kernel_launch(void* const* d_in, const int* in_sizes, int n_in,
                              void* d_out, int out_size) {
    (void)in_sizes; (void)n_in; (void)out_size;
    const float* x       = (const float*)d_in[0];
    const float* mask    = (const float*)d_in[1];
    const float* qkv_w   = (const float*)d_in[2];
    const float* qkv_b   = (const float*)d_in[3];
    const float* proj_w  = (const float*)d_in[4];
    const float* proj_b  = (const float*)d_in[5];
    const float* pposw   = (const float*)d_in[6];
    const float* pposb   = (const float*)d_in[7];
    const float* ln1g    = (const float*)d_in[8];
    const float* ln1b    = (const float*)d_in[9];
    const float* fc1w    = (const float*)d_in[10];
    const float* fc1b    = (const float*)d_in[11];
    const float* ln2g    = (const float*)d_in[12];
    const float* ln2b    = (const float*)d_in[13];
    const float* fc2w    = (const float*)d_in[14];
    const float* fc2b    = (const float*)d_in[15];
    const float* ln3g    = (const float*)d_in[16];
    const float* ln3b    = (const float*)d_in[17];
    const float* fc3w    = (const float*)d_in[18];
    const float* fc3b    = (const float*)d_in[19];
    const float* biases  = (const float*)d_in[20];
    const int*   rel_idx = (const int*)d_in[21];
    float* out = (float*)d_out;

    dpb_kernel<<<1, 256>>>(biases, pposw, pposb, ln1g, ln1b, fc1w, fc1b,
                           ln2g, ln2b, fc2w, fc2b, ln3g, ln3b, fc3w, fc3b);
    wsplit_kernel<<<512, 256>>>(qkv_w, proj_w);
    gemm_kernel<0><<<dim3(6, 1568), 256>>>(x, qkv_b, nullptr);
    attn_kernel<<<dim3(B_WIN, HEADS), 128>>>(mask, rel_idx);
    gemm_kernel<1><<<dim3(2, 1568), 256>>>(nullptr, proj_b, out);
}

// round 5
// speedup vs baseline: 1.3205x; 1.3205x over previous
#include <cuda_runtime.h>
#include <cuda_bf16.h>
#include <cstdint>
#include <math.h>

#define B_WIN   3136
#define NTOK    64
#define DIM     256
#define HEADS   8
#define NW      49
#define LBIAS   225
#define ATT_SCALE 0.17677669529663687f  // 1/sqrt(32)

// Scratch (device globals; alloc APIs forbidden)
__device__ uint2 g_x2 [25690112];  // x pre-split [M][128]
__device__ uint2 g_q2 [25690112];  // [B_*H][64][16]
__device__ uint2 g_k2 [25690112];
__device__ float g_v  [51380224];  // [B_*H][64][32] fp32
__device__ uint2 g_ot2[25690112];  // [B_*64][128] ctx pre-split
__device__ uint2 g_wq [98304];     // qkv_w pre-split [768][128]
__device__ uint2 g_wp [32768];     // proj_w pre-split [256][128]
__device__ float g_ptab[LBIAS * HEADS];
__device__ float g_bm  [1605632];  // combined bias+mask [49][8][64][64]

// ---------------------------------------------------------------------------
__device__ __forceinline__ void split2(float x, float y, uint32_t& hi, uint32_t& lo) {
    __nv_bfloat162 h = __floats2bfloat162_rn(x, y);
    float hx = __low2float(h), hy = __high2float(h);
    __nv_bfloat162 l = __floats2bfloat162_rn(x - hx, y - hy);
    hi = *reinterpret_cast<uint32_t*>(&h);
    lo = *reinterpret_cast<uint32_t*>(&l);
}

__device__ __forceinline__ void mma_bf16(float* c, const uint32_t* a, uint32_t b0, uint32_t b1) {
    asm volatile(
        "mma.sync.aligned.m16n8k16.row.col.f32.bf16.bf16.f32 "
        "{%0,%1,%2,%3}, {%4,%5,%6,%7}, {%8,%9}, {%0,%1,%2,%3};\n"
        : "+f"(c[0]), "+f"(c[1]), "+f"(c[2]), "+f"(c[3])
        : "r"(a[0]), "r"(a[1]), "r"(a[2]), "r"(a[3]), "r"(b0), "r"(b1));
}

__device__ __forceinline__ void ldgsts16(void* sp, const void* gp) {
    uint32_t sa = (uint32_t)__cvta_generic_to_shared(sp);
    asm volatile("cp.async.cg.shared.global [%0], [%1], 16;\n" :: "r"(sa), "l"(gp));
}

// ---------------------------------------------------------------------------
// Kernel 1: DynamicPosBias MLP -> g_ptab[225][8]  (fp32 exact)
// ---------------------------------------------------------------------------
__device__ __forceinline__ void lnrelu16(const float* p, float* t,
                                         const float* gm, const float* bt) {
    float m = 0.f;
#pragma unroll
    for (int j = 0; j < 16; j++) m += p[j];
    m *= (1.f / 16.f);
    float v = 0.f;
#pragma unroll
    for (int j = 0; j < 16; j++) { float d = p[j] - m; v += d * d; }
    v *= (1.f / 16.f);
    float is = rsqrtf(v + 1e-5f);
#pragma unroll
    for (int j = 0; j < 16; j++) {
        float u = (p[j] - m) * is * gm[j] + bt[j];
        t[j] = u > 0.f ? u : 0.f;
    }
}

__global__ void dpb_kernel(const float* __restrict__ biases,
                           const float* __restrict__ pw, const float* __restrict__ pb,
                           const float* __restrict__ g1, const float* __restrict__ b1,
                           const float* __restrict__ w1, const float* __restrict__ c1,
                           const float* __restrict__ g2, const float* __restrict__ b2,
                           const float* __restrict__ w2, const float* __restrict__ c2,
                           const float* __restrict__ g3, const float* __restrict__ b3,
                           const float* __restrict__ w3, const float* __restrict__ c3) {
    int r = threadIdx.x;
    if (r >= LBIAS) return;
    float p[16], t[16];
    float x0 = biases[2 * r], x1 = biases[2 * r + 1];
#pragma unroll
    for (int j = 0; j < 16; j++) p[j] = x0 * pw[2 * j] + x1 * pw[2 * j + 1] + pb[j];
    lnrelu16(p, t, g1, b1);
#pragma unroll
    for (int o = 0; o < 16; o++) {
        float s = c1[o];
#pragma unroll
        for (int j = 0; j < 16; j++) s += t[j] * w1[o * 16 + j];
        p[o] = s;
    }
    lnrelu16(p, t, g2, b2);
#pragma unroll
    for (int o = 0; o < 16; o++) {
        float s = c2[o];
#pragma unroll
        for (int j = 0; j < 16; j++) s += t[j] * w2[o * 16 + j];
        p[o] = s;
    }
    lnrelu16(p, t, g3, b3);
#pragma unroll
    for (int o = 0; o < 8; o++) {
        float s = c3[o];
#pragma unroll
        for (int j = 0; j < 16; j++) s += t[j] * w3[o * 16 + j];
        g_ptab[r * 8 + o] = s;
    }
}

// ---------------------------------------------------------------------------
// Kernel 1b: pre-split x + weights into packed hi/lo uint2 tables
// ---------------------------------------------------------------------------
__global__ void presplit_kernel(const float* __restrict__ x,
                                const float* __restrict__ qw,
                                const float* __restrict__ pw) {
    int i = blockIdx.x * blockDim.x + threadIdx.x;
    if (i < 25690112) {
        float2 f = ((const float2*)x)[i];
        split2(f.x, f.y, g_x2[i].x, g_x2[i].y);
    } else if (i < 25690112 + 98304) {
        int j = i - 25690112;
        float2 f = ((const float2*)qw)[j];
        split2(f.x, f.y, g_wq[j].x, g_wq[j].y);
    } else if (i < 25690112 + 98304 + 32768) {
        int j = i - 25690112 - 98304;
        float2 f = ((const float2*)pw)[j];
        split2(f.x, f.y, g_wp[j].x, g_wp[j].y);
    }
}

// ---------------------------------------------------------------------------
// Kernel 1c: combined bias+mask table (runs after dpb_kernel)
// ---------------------------------------------------------------------------
__global__ void bmtab_kernel(const float* __restrict__ mask,
                             const int* __restrict__ rel_idx) {
    int wb = blockIdx.x, h = blockIdx.y;
    float* dst = g_bm + (size_t)(wb * 8 + h) * 4096;
    const float* msk = mask + (size_t)wb * 4096;
    for (int i = threadIdx.x; i < 4096; i += blockDim.x)
        dst[i] = g_ptab[rel_idx[i] * 8 + h] + msk[i];
}

// ---------------------------------------------------------------------------
// Kernel 2/4: Y[M,NO] = A[M,256] @ W[NO,256]^T + bias ; BM=BN=128, BK=32.
// All operands pre-split uint2. cp.async 2-stage pipeline, 80KB dynamic smem.
// MODE 0: A=g_x2, B=g_wq, epilogue scatters q/k/v. MODE 1: A=g_ot2, B=g_wp.
// ---------------------------------------------------------------------------
template <int MODE>
__global__ __launch_bounds__(256, 2) void gemm_kernel(const float* __restrict__ bias,
                                                      float* __restrict__ Out) {
    extern __shared__ uint2 smbuf[];   // [2][A:2560 | B:2560]

    int bm = blockIdx.y, bn = blockIdx.x;
    int tid = threadIdx.x;
    int warp = tid >> 5, lane = tid & 31;
    int wm = warp >> 1, wn = warp & 1;
    int g = lane >> 2, tg = lane & 3;

    const uint2* Asrc = (MODE ? g_ot2 : g_x2) + (size_t)bm * 128 * 128;
    const uint2* Bsrc = (MODE ? g_wp : g_wq) + (size_t)bn * 128 * 128;

    float acc[2][8][4];
#pragma unroll
    for (int a = 0; a < 2; a++)
#pragma unroll
        for (int b = 0; b < 8; b++)
#pragma unroll
            for (int c = 0; c < 4; c++) acc[a][b][c] = 0.f;

    auto issue_tile = [&](int kb, int s) {
        uint2* As = smbuf + s * 5120;
        uint2* Bs = As + 2560;
#pragma unroll
        for (int k = 0; k < 4; k++) {
            int c = tid + k * 256;
            int r = c >> 3, j = (c & 7) * 2;
            ldgsts16(&As[r * 20 + j], Asrc + (size_t)r * 128 + kb * 16 + j);
            ldgsts16(&Bs[r * 20 + j], Bsrc + (size_t)r * 128 + kb * 16 + j);
        }
        asm volatile("cp.async.commit_group;\n");
    };

    int mr = wm * 32;
    issue_tile(0, 0);

    for (int kb = 0; kb < 8; kb++) {
        int s = kb & 1;
        if (kb < 7) {
            issue_tile(kb + 1, s ^ 1);
            asm volatile("cp.async.wait_group 1;\n");
        } else {
            asm volatile("cp.async.wait_group 0;\n");
        }
        __syncthreads();

        const uint2* As = smbuf + s * 5120;
        const uint2* Bs = As + 2560;
#pragma unroll
        for (int ks = 0; ks < 2; ks++) {
            int j0 = ks * 8;
            uint32_t ah0[4], al0[4], ah1[4], al1[4];
            {
                uint2 t;
                t = As[(mr + g) * 20 + j0 + tg];          ah0[0] = t.x; al0[0] = t.y;
                t = As[(mr + g + 8) * 20 + j0 + tg];      ah0[1] = t.x; al0[1] = t.y;
                t = As[(mr + g) * 20 + j0 + tg + 4];      ah0[2] = t.x; al0[2] = t.y;
                t = As[(mr + g + 8) * 20 + j0 + tg + 4];  ah0[3] = t.x; al0[3] = t.y;
                t = As[(mr + 16 + g) * 20 + j0 + tg];         ah1[0] = t.x; al1[0] = t.y;
                t = As[(mr + 16 + g + 8) * 20 + j0 + tg];     ah1[1] = t.x; al1[1] = t.y;
                t = As[(mr + 16 + g) * 20 + j0 + tg + 4];     ah1[2] = t.x; al1[2] = t.y;
                t = As[(mr + 16 + g + 8) * 20 + j0 + tg + 4]; ah1[3] = t.x; al1[3] = t.y;
            }
#pragma unroll
            for (int nfp = 0; nfp < 4; nfp++) {
                int nf0 = 2 * nfp, nf1 = nf0 + 1;
                int nA = wn * 64 + nf0 * 8 + g;
                uint2 c0 = Bs[nA * 20 + j0 + tg],       c1 = Bs[nA * 20 + j0 + tg + 4];
                uint2 d0 = Bs[(nA + 8) * 20 + j0 + tg], d1 = Bs[(nA + 8) * 20 + j0 + tg + 4];
                mma_bf16(acc[0][nf0], ah0, c0.x, c1.x);
                mma_bf16(acc[1][nf0], ah1, c0.x, c1.x);
                mma_bf16(acc[0][nf1], ah0, d0.x, d1.x);
                mma_bf16(acc[1][nf1], ah1, d0.x, d1.x);
                mma_bf16(acc[0][nf0], ah0, c0.y, c1.y);
                mma_bf16(acc[1][nf0], ah1, c0.y, c1.y);
                mma_bf16(acc[0][nf1], ah0, d0.y, d1.y);
                mma_bf16(acc[1][nf1], ah1, d0.y, d1.y);
                mma_bf16(acc[0][nf0], al0, c0.x, c1.x);
                mma_bf16(acc[1][nf0], al1, c0.x, c1.x);
                mma_bf16(acc[0][nf1], al0, d0.x, d1.x);
                mma_bf16(acc[1][nf1], al1, d0.x, d1.x);
            }
        }
        __syncthreads();
    }

    int obase = bn * 128 + wn * 64;
#pragma unroll
    for (int nf = 0; nf < 8; nf++) {
        int o = obase + nf * 8 + 2 * tg;
        float bb0 = bias[o], bb1 = bias[o + 1];
#pragma unroll
        for (int mf = 0; mf < 2; mf++) {
#pragma unroll
            for (int r2 = 0; r2 < 2; r2++) {
                int m = bm * 128 + wm * 32 + mf * 16 + g + r2 * 8;
                float v0 = acc[mf][nf][r2 * 2] + bb0;
                float v1 = acc[mf][nf][r2 * 2 + 1] + bb1;
                if (MODE == 1) {
                    *(float2*)(Out + (size_t)m * 256 + o) = make_float2(v0, v1);
                } else {
                    int s = o >> 8, hh = (o >> 5) & 7, d = o & 31;
                    int bw = m >> 6, n = m & 63;
                    size_t di = ((size_t)(bw * 8 + hh) * 64 + n) * 16 + (d >> 1);
                    if (s == 0) {
                        uint2 u; split2(v0 * ATT_SCALE, v1 * ATT_SCALE, u.x, u.y);
                        g_q2[di] = u;
                    } else if (s == 1) {
                        uint2 u; split2(v0, v1, u.x, u.y);
                        g_k2[di] = u;
                    } else {
                        *(float2*)(g_v + (di << 1)) = make_float2(v0, v1);
                    }
                }
            }
        }
    }
}

// ---------------------------------------------------------------------------
// Kernel 3: attention per (window b, head h). 4 warps, 16 query rows each.
// q fragments direct from gmem; k/v via smem; single __syncthreads.
// ---------------------------------------------------------------------------
__global__ __launch_bounds__(128, 5) void attn_kernel() {
    __shared__ uint2 k2s[64][20];
    __shared__ uint2 vt2[32][36];   // V^T: [d][token-pair]
    __shared__ uint2 p2 [64][36];   // probs

    int b = blockIdx.x, h = blockIdx.y;
    int tid = threadIdx.x;
    int warp = tid >> 5, lane = tid & 31;
    int g = lane >> 2, tg = lane & 3;
    int mr = warp * 16;

    const uint2* qg = g_q2 + (size_t)(b * 8 + h) * 1024;
    const uint2* kg = g_k2 + (size_t)(b * 8 + h) * 1024;
    const float* vg = g_v  + (size_t)(b * 8 + h) * 2048;

    // q fragments straight from gmem (warp-coalesced LDG.64)
    uint32_t qh_[2][4], ql_[2][4];
#pragma unroll
    for (int ks = 0; ks < 2; ks++) {
        int j0 = ks * 8;
        uint2 t;
        t = qg[(mr + g) * 16 + j0 + tg];          qh_[ks][0] = t.x; ql_[ks][0] = t.y;
        t = qg[(mr + g + 8) * 16 + j0 + tg];      qh_[ks][1] = t.x; ql_[ks][1] = t.y;
        t = qg[(mr + g) * 16 + j0 + tg + 4];      qh_[ks][2] = t.x; ql_[ks][2] = t.y;
        t = qg[(mr + g + 8) * 16 + j0 + tg + 4];  qh_[ks][3] = t.x; ql_[ks][3] = t.y;
    }

    for (int it = tid; it < 1024; it += 128) {
        int t = it >> 4, j = it & 15;
        k2s[t][j] = kg[it];
    }
    for (int it = tid; it < 1024; it += 128) {
        int d = it & 31, j = it >> 5;
        uint2 u;
        split2(vg[(2 * j) * 32 + d], vg[(2 * j + 1) * 32 + d], u.x, u.y);
        vt2[d][j] = u;
    }
    __syncthreads();

    // logits = q @ k^T  (q pre-scaled)
    float acc[8][4];
#pragma unroll
    for (int a = 0; a < 8; a++)
#pragma unroll
        for (int c = 0; c < 4; c++) acc[a][c] = 0.f;

#pragma unroll
    for (int ks = 0; ks < 2; ks++) {
        int j0 = ks * 8;
#pragma unroll
        for (int nfp = 0; nfp < 4; nfp++) {
            int nf0 = 2 * nfp, nf1 = nf0 + 1;
            int n0 = nf0 * 8 + g;
            uint2 c0 = k2s[n0][j0 + tg],     c1 = k2s[n0][j0 + tg + 4];
            uint2 d0 = k2s[n0 + 8][j0 + tg], d1 = k2s[n0 + 8][j0 + tg + 4];
            mma_bf16(acc[nf0], qh_[ks], c0.x, c1.x);
            mma_bf16(acc[nf1], qh_[ks], d0.x, d1.x);
            mma_bf16(acc[nf0], qh_[ks], c0.y, c1.y);
            mma_bf16(acc[nf1], qh_[ks], d0.y, d1.y);
            mma_bf16(acc[nf0], ql_[ks], c0.x, c1.x);
            mma_bf16(acc[nf1], ql_[ks], d0.x, d1.x);
        }
    }

    // combined bias+mask from precomputed table
    int r0 = mr + g, r1 = r0 + 8;
    const float* bmr = g_bm + (size_t)((b % NW) * 8 + h) * 4096;
#pragma unroll
    for (int nf = 0; nf < 8; nf++) {
        int n0 = nf * 8 + 2 * tg;
        float2 e0 = *(const float2*)(bmr + r0 * 64 + n0);
        float2 e1 = *(const float2*)(bmr + r1 * 64 + n0);
        acc[nf][0] += e0.x; acc[nf][1] += e0.y;
        acc[nf][2] += e1.x; acc[nf][3] += e1.y;
    }

    // softmax across the quad (rows r0, r1)
    float m0 = -1e30f, m1 = -1e30f;
#pragma unroll
    for (int nf = 0; nf < 8; nf++) {
        m0 = fmaxf(m0, fmaxf(acc[nf][0], acc[nf][1]));
        m1 = fmaxf(m1, fmaxf(acc[nf][2], acc[nf][3]));
    }
    m0 = fmaxf(m0, __shfl_xor_sync(0xffffffffu, m0, 1));
    m0 = fmaxf(m0, __shfl_xor_sync(0xffffffffu, m0, 2));
    m1 = fmaxf(m1, __shfl_xor_sync(0xffffffffu, m1, 1));
    m1 = fmaxf(m1, __shfl_xor_sync(0xffffffffu, m1, 2));

    float s0 = 0.f, s1 = 0.f;
#pragma unroll
    for (int nf = 0; nf < 8; nf++) {
        acc[nf][0] = __expf(acc[nf][0] - m0); s0 += acc[nf][0];
        acc[nf][1] = __expf(acc[nf][1] - m0); s0 += acc[nf][1];
        acc[nf][2] = __expf(acc[nf][2] - m1); s1 += acc[nf][2];
        acc[nf][3] = __expf(acc[nf][3] - m1); s1 += acc[nf][3];
    }
    s0 += __shfl_xor_sync(0xffffffffu, s0, 1);
    s0 += __shfl_xor_sync(0xffffffffu, s0, 2);
    s1 += __shfl_xor_sync(0xffffffffu, s1, 1);
    s1 += __shfl_xor_sync(0xffffffffu, s1, 2);
    float i0 = 1.f / s0, i1 = 1.f / s1;

#pragma unroll
    for (int nf = 0; nf < 8; nf++) {
        uint2 u;
        split2(acc[nf][0] * i0, acc[nf][1] * i0, u.x, u.y); p2[r0][nf * 4 + tg] = u;
        split2(acc[nf][2] * i1, acc[nf][3] * i1, u.x, u.y); p2[r1][nf * 4 + tg] = u;
    }
    __syncwarp();

    // out = P @ V
    float oacc[4][4];
#pragma unroll
    for (int a = 0; a < 4; a++)
#pragma unroll
        for (int c = 0; c < 4; c++) oacc[a][c] = 0.f;

#pragma unroll
    for (int ks = 0; ks < 4; ks++) {
        int j0 = ks * 8;
        uint32_t ah[4], al[4];
        {
            uint2 t;
            t = p2[mr + g][j0 + tg];          ah[0] = t.x; al[0] = t.y;
            t = p2[mr + g + 8][j0 + tg];      ah[1] = t.x; al[1] = t.y;
            t = p2[mr + g][j0 + tg + 4];      ah[2] = t.x; al[2] = t.y;
            t = p2[mr + g + 8][j0 + tg + 4];  ah[3] = t.x; al[3] = t.y;
        }
#pragma unroll
        for (int nfp = 0; nfp < 2; nfp++) {
            int nf0 = 2 * nfp, nf1 = nf0 + 1;
            int n0 = nf0 * 8 + g;
            uint2 c0 = vt2[n0][j0 + tg],     c1 = vt2[n0][j0 + tg + 4];
            uint2 d0 = vt2[n0 + 8][j0 + tg], d1 = vt2[n0 + 8][j0 + tg + 4];
            mma_bf16(oacc[nf0], ah, c0.x, c1.x);
            mma_bf16(oacc[nf1], ah, d0.x, d1.x);
            mma_bf16(oacc[nf0], ah, c0.y, c1.y);
            mma_bf16(oacc[nf1], ah, d0.y, d1.y);
            mma_bf16(oacc[nf0], al, c0.x, c1.x);
            mma_bf16(oacc[nf1], al, d0.x, d1.x);
        }
    }

    // ctx -> g_ot2[(b*64+n)][h*16 + dpair]
#pragma unroll
    for (int nf = 0; nf < 4; nf++) {
        int dp = h * 16 + nf * 4 + tg;
        uint2 u;
        split2(oacc[nf][0], oacc[nf][1], u.x, u.y);
        g_ot2[(size_t)(b * 64 + r0) * 128 + dp] = u;
        split2(oacc[nf][2], oacc[nf][3], u.x, u.y);
        g_ot2[(size_t)(b * 64 + r1) * 128 + dp] = u;
    }
}

// ---------------------------------------------------------------------------
extern "C" void kernel_launch(void* const* d_in, const int* in_sizes, int n_in,
                              void* d_out, int out_size) {
    (void)in_sizes; (void)n_in; (void)out_size;
    const float* x       = (const float*)d_in[0];
    const float* mask    = (const float*)d_in[1];
    const float* qkv_w   = (const float*)d_in[2];
    const float* qkv_b   = (const float*)d_in[3];
    const float* proj_w  = (const float*)d_in[4];
    const float* proj_b  = (const float*)d_in[5];
    const float* pposw   = (const float*)d_in[6];
    const float* pposb   = (const float*)d_in[7];
    const float* ln1g    = (const float*)d_in[8];
    const float* ln1b    = (const float*)d_in[9];
    const float* fc1w    = (const float*)d_in[10];
    const float* fc1b    = (const float*)d_in[11];
    const float* ln2g    = (const float*)d_in[12];
    const float* ln2b    = (const float*)d_in[13];
    const float* fc2w    = (const float*)d_in[14];
    const float* fc2b    = (const float*)d_in[15];
    const float* ln3g    = (const float*)d_in[16];
    const float* ln3b    = (const float*)d_in[17];
    const float* fc3w    = (const float*)d_in[18];
    const float* fc3b    = (const float*)d_in[19];
    const float* biases  = (const float*)d_in[20];
    const int*   rel_idx = (const int*)d_in[21];
    float* out = (float*)d_out;

    static bool attr_set = false;
    if (!attr_set) {
        cudaFuncSetAttribute(gemm_kernel<0>, cudaFuncAttributeMaxDynamicSharedMemorySize, 81920);
        cudaFuncSetAttribute(gemm_kernel<1>, cudaFuncAttributeMaxDynamicSharedMemorySize, 81920);
        attr_set = true;
    }

    dpb_kernel<<<1, 256>>>(biases, pposw, pposb, ln1g, ln1b, fc1w, fc1b,
                           ln2g, ln2b, fc2w, fc2b, ln3g, ln3b, fc3w, fc3b);
    presplit_kernel<<<100904, 256>>>(x, qkv_w, proj_w);
    bmtab_kernel<<<dim3(NW, HEADS), 256>>>(mask, rel_idx);
    gemm_kernel<0><<<dim3(6, 1568), 256, 81920>>>(qkv_b, nullptr);
    attn_kernel<<<dim3(B_WIN, HEADS), 128>>>();
    gemm_kernel<1><<<dim3(2, 1568), 256, 81920>>>(proj_b, out);
}

// round 7
// speedup vs baseline: 1.6501x; 1.2496x over previous
#include <cuda_runtime.h>
#include <cuda_bf16.h>
#include <cstdint>
#include <math.h>

#define B_WIN   3136
#define NTOK    64
#define DIM     256
#define HEADS   8
#define NW      49
#define LBIAS   225
#define ATT_SCALE 0.17677669529663687f  // 1/sqrt(32)

// ---------------------------------------------------------------------------
// Plane layout: per (tile128, kchunk32) chunk of a [rows][256] bf16 matrix,
// 2048 uint32 pairs (8KB). Row r (0..127), pair q (0..15, k=2q within chunk):
//   j = r>>1 (128B smem row), unit = (((r&1)<<2) | (q>>2)) ^ (j&7)
//   pair index = j*32 + unit*4 + (q&3)
// Identical bytes in gmem and smem -> GEMM loader is a straight 16B memcpy,
// and ldmatrix addresses swizzle conflict-free.
// ---------------------------------------------------------------------------
__device__ uint32_t g_xhi [25690112];  // x planes
__device__ uint32_t g_xlo [25690112];
__device__ uint32_t g_othi[25690112];  // ctx planes
__device__ uint32_t g_otlo[25690112];
__device__ uint32_t g_wqh [98304];     // qkv_w planes
__device__ uint32_t g_wql [98304];
__device__ uint32_t g_wph [32768];     // proj_w planes
__device__ uint32_t g_wpl [32768];
__device__ uint2    g_q2  [25690112];  // [B_*H][64][16] packed hi/lo
__device__ uint2    g_k2  [25690112];
__device__ float    g_v   [51380224];  // [B_*H][64][32] fp32
__device__ float    g_ptab[LBIAS * HEADS];
__device__ float    g_bm  [1605632];   // bias+mask [49][8][64][64]

// ---------------------------------------------------------------------------
__device__ __forceinline__ void split2(float x, float y, uint32_t& hi, uint32_t& lo) {
    __nv_bfloat162 h = __floats2bfloat162_rn(x, y);
    float hx = __low2float(h), hy = __high2float(h);
    __nv_bfloat162 l = __floats2bfloat162_rn(x - hx, y - hy);
    hi = *reinterpret_cast<uint32_t*>(&h);
    lo = *reinterpret_cast<uint32_t*>(&l);
}

__device__ __forceinline__ uint32_t plane_pair(int r, int q) {
    int j = r >> 1;
    int u = (((r & 1) << 2) | (q >> 2)) ^ (j & 7);
    return (uint32_t)(j * 32 + u * 4 + (q & 3));
}

__device__ __forceinline__ void mma_bf16(float* c, const uint32_t* a, uint32_t b0, uint32_t b1) {
    asm volatile(
        "mma.sync.aligned.m16n8k16.row.col.f32.bf16.bf16.f32 "
        "{%0,%1,%2,%3}, {%4,%5,%6,%7}, {%8,%9}, {%0,%1,%2,%3};\n"
        : "+f"(c[0]), "+f"(c[1]), "+f"(c[2]), "+f"(c[3])
        : "r"(a[0]), "r"(a[1]), "r"(a[2]), "r"(a[3]), "r"(b0), "r"(b1));
}

__device__ __forceinline__ void ldsm4(uint32_t* r, uint32_t a) {
    asm volatile("ldmatrix.sync.aligned.m8n8.x4.shared.b16 {%0,%1,%2,%3}, [%4];"
                 : "=r"(r[0]), "=r"(r[1]), "=r"(r[2]), "=r"(r[3]) : "r"(a));
}

__device__ __forceinline__ void ldgsts16(uint32_t saddr, const void* gp) {
    asm volatile("cp.async.cg.shared.global [%0], [%1], 16;\n" :: "r"(saddr), "l"(gp));
}

// ---------------------------------------------------------------------------
// Kernel 1: DynamicPosBias MLP -> g_ptab[225][8]  (fp32 exact)
// ---------------------------------------------------------------------------
__device__ __forceinline__ void lnrelu16(const float* p, float* t,
                                         const float* gm, const float* bt) {
    float m = 0.f;
#pragma unroll
    for (int j = 0; j < 16; j++) m += p[j];
    m *= (1.f / 16.f);
    float v = 0.f;
#pragma unroll
    for (int j = 0; j < 16; j++) { float d = p[j] - m; v += d * d; }
    v *= (1.f / 16.f);
    float is = rsqrtf(v + 1e-5f);
#pragma unroll
    for (int j = 0; j < 16; j++) {
        float u = (p[j] - m) * is * gm[j] + bt[j];
        t[j] = u > 0.f ? u : 0.f;
    }
}

__global__ void dpb_kernel(const float* __restrict__ biases,
                           const float* __restrict__ pw, const float* __restrict__ pb,
                           const float* __restrict__ g1, const float* __restrict__ b1,
                           const float* __restrict__ w1, const float* __restrict__ c1,
                           const float* __restrict__ g2, const float* __restrict__ b2,
                           const float* __restrict__ w2, const float* __restrict__ c2,
                           const float* __restrict__ g3, const float* __restrict__ b3,
                           const float* __restrict__ w3, const float* __restrict__ c3) {
    int r = threadIdx.x;
    if (r >= LBIAS) return;
    float p[16], t[16];
    float x0 = biases[2 * r], x1 = biases[2 * r + 1];
#pragma unroll
    for (int j = 0; j < 16; j++) p[j] = x0 * pw[2 * j] + x1 * pw[2 * j + 1] + pb[j];
    lnrelu16(p, t, g1, b1);
#pragma unroll
    for (int o = 0; o < 16; o++) {
        float s = c1[o];
#pragma unroll
        for (int j = 0; j < 16; j++) s += t[j] * w1[o * 16 + j];
        p[o] = s;
    }
    lnrelu16(p, t, g2, b2);
#pragma unroll
    for (int o = 0; o < 16; o++) {
        float s = c2[o];
#pragma unroll
        for (int j = 0; j < 16; j++) s += t[j] * w2[o * 16 + j];
        p[o] = s;
    }
    lnrelu16(p, t, g3, b3);
#pragma unroll
    for (int o = 0; o < 8; o++) {
        float s = c3[o];
#pragma unroll
        for (int j = 0; j < 16; j++) s += t[j] * w3[o * 16 + j];
        g_ptab[r * 8 + o] = s;
    }
}

// ---------------------------------------------------------------------------
// Kernel 1b: pre-split x / qkv_w / proj_w into plane chunks
// ---------------------------------------------------------------------------
__global__ void presplit_kernel(const float* __restrict__ x,
                                const float* __restrict__ qw,
                                const float* __restrict__ pw) {
    long i = (long)blockIdx.x * 256 + threadIdx.x;
    const float2* src; uint32_t *dh, *dl; long j;
    if (i < 25690112L) { j = i; src = (const float2*)x; dh = g_xhi; dl = g_xlo; }
    else if (i < 25690112L + 98304) { j = i - 25690112L; src = (const float2*)qw; dh = g_wqh; dl = g_wql; }
    else if (i < 25690112L + 98304 + 32768) { j = i - 25690112L - 98304; src = (const float2*)pw; dh = g_wph; dl = g_wpl; }
    else return;
    int m = (int)(j >> 7);
    int pc = (int)(j & 127);
    int tile = m >> 7, r = m & 127;
    int kb = pc >> 4, q = pc & 15;
    long idx = ((long)(tile * 8 + kb)) * 2048 + plane_pair(r, q);
    float2 f = src[j];
    uint32_t hi, lo;
    split2(f.x, f.y, hi, lo);
    dh[idx] = hi;
    dl[idx] = lo;
}

// ---------------------------------------------------------------------------
// Kernel 1c: combined bias+mask table
// ---------------------------------------------------------------------------
__global__ void bmtab_kernel(const float* __restrict__ mask,
                             const int* __restrict__ rel_idx) {
    int wb = blockIdx.x, h = blockIdx.y;
    float* dst = g_bm + (size_t)(wb * 8 + h) * 4096;
    const float* msk = mask + (size_t)wb * 4096;
    for (int i = threadIdx.x; i < 4096; i += blockDim.x)
        dst[i] = g_ptab[rel_idx[i] * 8 + h] + msk[i];
}

// ---------------------------------------------------------------------------
// Kernel 2/4: HMMA GEMM, BM=BN=128, K=256 in 8 chunks of 32.
// ldmatrix fragments from hi/lo planes; cp.async 3-stage (32KB/stage).
// MODE 0: A=x planes, B=qkv_w planes -> scatter q/k/v.
// MODE 1: A=ctx planes, B=proj_w planes -> Out.
// ---------------------------------------------------------------------------
template <int MODE>
__global__ __launch_bounds__(256, 2) void gemm_kernel(const float* __restrict__ bias,
                                                      float* __restrict__ Out) {
    extern __shared__ char smem[];
    uint32_t sb = (uint32_t)__cvta_generic_to_shared(smem);

    int bm = blockIdx.y, bn = blockIdx.x;
    int tid = threadIdx.x;
    int warp = tid >> 5, lane = tid & 31;
    int wm = warp >> 1, wn = warp & 1;
    int g = lane >> 2, tg = lane & 3;

    const uint32_t* Ah = MODE ? g_othi : g_xhi;
    const uint32_t* Al = MODE ? g_otlo : g_xlo;
    const uint32_t* Bh = MODE ? g_wph : g_wqh;
    const uint32_t* Bl = MODE ? g_wpl : g_wql;

    float acc[2][8][4];
#pragma unroll
    for (int a = 0; a < 2; a++)
#pragma unroll
        for (int b = 0; b < 8; b++)
#pragma unroll
            for (int c = 0; c < 4; c++) acc[a][b][c] = 0.f;

    // ldmatrix per-lane bases
    auto mkbase = [&](int r, int lb) {
        int j = r >> 1, a = (r & 1) << 2;
        return (uint32_t)(j * 128 + (((a ^ lb) ^ (j & 7)) << 4));
    };
    int rA = lane & 15, lbA = lane >> 4;
    uint32_t baseA0 = mkbase(wm * 32 + rA, lbA);
    uint32_t baseA1 = mkbase(wm * 32 + 16 + rA, lbA);
    int rB = (lane & 7) | ((lane >> 1) & 8);
    int lbB = (lane >> 3) & 1;
    uint32_t baseB[4];
#pragma unroll
    for (int i = 0; i < 4; i++) baseB[i] = mkbase(wn * 64 + i * 16 + rB, lbB);

    auto issue = [&](int kb, int s) {
        uint32_t S = sb + (uint32_t)s * 32768;
        const uint32_t* srcs[4] = {
            Ah + (size_t)(bm * 8 + kb) * 2048, Al + (size_t)(bm * 8 + kb) * 2048,
            Bh + (size_t)(bn * 8 + kb) * 2048, Bl + (size_t)(bn * 8 + kb) * 2048 };
#pragma unroll
        for (int p = 0; p < 4; p++) {
#pragma unroll
            for (int e = 0; e < 2; e++) {
                int u = tid + e * 256;  // 16B unit, 512 per plane
                ldgsts16(S + (uint32_t)p * 8192 + u * 16, srcs[p] + u * 4);
            }
        }
        asm volatile("cp.async.commit_group;\n" ::: "memory");
    };

    issue(0, 0);
    issue(1, 1);

    for (int kb = 0; kb < 8; kb++) {
        int s = kb % 3;
        if (kb < 7) asm volatile("cp.async.wait_group 1;\n" ::: "memory");
        else        asm volatile("cp.async.wait_group 0;\n" ::: "memory");
        __syncthreads();

        uint32_t S = sb + (uint32_t)s * 32768;
#pragma unroll
        for (int ks = 0; ks < 2; ks++) {
            uint32_t uo = ks * 32;
            uint32_t ah0[4], ah1[4], al0[4], al1[4];
            ldsm4(ah0, S + (baseA0 ^ uo));
            ldsm4(ah1, S + (baseA1 ^ uo));
            ldsm4(al0, S + 8192 + (baseA0 ^ uo));
            ldsm4(al1, S + 8192 + (baseA1 ^ uo));
#pragma unroll
            for (int nfp = 0; nfp < 4; nfp++) {
                int nf0 = 2 * nfp, nf1 = nf0 + 1;
                uint32_t bh[4], bl[4];
                ldsm4(bh, S + 16384 + (baseB[nfp] ^ uo));
                ldsm4(bl, S + 24576 + (baseB[nfp] ^ uo));
                mma_bf16(acc[0][nf0], ah0, bh[0], bh[1]);
                mma_bf16(acc[1][nf0], ah1, bh[0], bh[1]);
                mma_bf16(acc[0][nf1], ah0, bh[2], bh[3]);
                mma_bf16(acc[1][nf1], ah1, bh[2], bh[3]);
                mma_bf16(acc[0][nf0], ah0, bl[0], bl[1]);
                mma_bf16(acc[1][nf0], ah1, bl[0], bl[1]);
                mma_bf16(acc[0][nf1], ah0, bl[2], bl[3]);
                mma_bf16(acc[1][nf1], ah1, bl[2], bl[3]);
                mma_bf16(acc[0][nf0], al0, bh[0], bh[1]);
                mma_bf16(acc[1][nf0], al1, bh[0], bh[1]);
                mma_bf16(acc[0][nf1], al0, bh[2], bh[3]);
                mma_bf16(acc[1][nf1], al1, bh[2], bh[3]);
            }
        }
        if (kb < 6) issue(kb + 2, (kb + 2) % 3);
    }

    int obase = bn * 128 + wn * 64;
#pragma unroll
    for (int nf = 0; nf < 8; nf++) {
        int o = obase + nf * 8 + 2 * tg;
        float bb0 = bias[o], bb1 = bias[o + 1];
#pragma unroll
        for (int mf = 0; mf < 2; mf++) {
#pragma unroll
            for (int r2 = 0; r2 < 2; r2++) {
                int m = bm * 128 + wm * 32 + mf * 16 + g + r2 * 8;
                float v0 = acc[mf][nf][r2 * 2] + bb0;
                float v1 = acc[mf][nf][r2 * 2 + 1] + bb1;
                if (MODE == 1) {
                    *(float2*)(Out + (size_t)m * 256 + o) = make_float2(v0, v1);
                } else {
                    int s = o >> 8, hh = (o >> 5) & 7, d = o & 31;
                    int bw = m >> 6, n = m & 63;
                    size_t di = ((size_t)(bw * 8 + hh) * 64 + n) * 16 + (d >> 1);
                    if (s == 0)      { uint2 u; split2(v0 * ATT_SCALE, v1 * ATT_SCALE, u.x, u.y); g_q2[di] = u; }
                    else if (s == 1) { uint2 u; split2(v0, v1, u.x, u.y); g_k2[di] = u; }
                    else             { *(float2*)(g_v + (di << 1)) = make_float2(v0, v1); }
                }
            }
        }
    }
}

// ---------------------------------------------------------------------------
// Kernel 3: attention per (window b, head h). 4 warps, 16 query rows each.
// q fragments direct from gmem; k/v via smem; ctx -> proj operand planes.
// ---------------------------------------------------------------------------
__global__ __launch_bounds__(128, 5) void attn_kernel() {
    __shared__ uint2 k2s[64][20];
    __shared__ uint2 vt2[32][36];   // V^T: [d][token-pair]
    __shared__ uint2 p2 [64][36];   // probs

    int b = blockIdx.x, h = blockIdx.y;
    int tid = threadIdx.x;
    int warp = tid >> 5, lane = tid & 31;
    int g = lane >> 2, tg = lane & 3;
    int mr = warp * 16;

    const uint2* qg = g_q2 + (size_t)(b * 8 + h) * 1024;
    const uint2* kg = g_k2 + (size_t)(b * 8 + h) * 1024;
    const float* vg = g_v  + (size_t)(b * 8 + h) * 2048;

    uint32_t qh_[2][4], ql_[2][4];
#pragma unroll
    for (int ks = 0; ks < 2; ks++) {
        int j0 = ks * 8;
        uint2 t;
        t = qg[(mr + g) * 16 + j0 + tg];          qh_[ks][0] = t.x; ql_[ks][0] = t.y;
        t = qg[(mr + g + 8) * 16 + j0 + tg];      qh_[ks][1] = t.x; ql_[ks][1] = t.y;
        t = qg[(mr + g) * 16 + j0 + tg + 4];      qh_[ks][2] = t.x; ql_[ks][2] = t.y;
        t = qg[(mr + g + 8) * 16 + j0 + tg + 4];  qh_[ks][3] = t.x; ql_[ks][3] = t.y;
    }

    for (int it = tid; it < 1024; it += 128) {
        int t = it >> 4, j = it & 15;
        k2s[t][j] = kg[it];
    }
    for (int it = tid; it < 1024; it += 128) {
        int d = it & 31, j = it >> 5;
        uint2 u;
        split2(vg[(2 * j) * 32 + d], vg[(2 * j + 1) * 32 + d], u.x, u.y);
        vt2[d][j] = u;
    }
    __syncthreads();

    float acc[8][4];
#pragma unroll
    for (int a = 0; a < 8; a++)
#pragma unroll
        for (int c = 0; c < 4; c++) acc[a][c] = 0.f;

#pragma unroll
    for (int ks = 0; ks < 2; ks++) {
        int j0 = ks * 8;
#pragma unroll
        for (int nfp = 0; nfp < 4; nfp++) {
            int nf0 = 2 * nfp, nf1 = nf0 + 1;
            int n0 = nf0 * 8 + g;
            uint2 c0 = k2s[n0][j0 + tg],     c1 = k2s[n0][j0 + tg + 4];
            uint2 d0 = k2s[n0 + 8][j0 + tg], d1 = k2s[n0 + 8][j0 + tg + 4];
            mma_bf16(acc[nf0], qh_[ks], c0.x, c1.x);
            mma_bf16(acc[nf1], qh_[ks], d0.x, d1.x);
            mma_bf16(acc[nf0], qh_[ks], c0.y, c1.y);
            mma_bf16(acc[nf1], qh_[ks], d0.y, d1.y);
            mma_bf16(acc[nf0], ql_[ks], c0.x, c1.x);
            mma_bf16(acc[nf1], ql_[ks], d0.x, d1.x);
        }
    }

    int r0 = mr + g, r1 = r0 + 8;
    const float* bmr = g_bm + (size_t)((b % NW) * 8 + h) * 4096;
#pragma unroll
    for (int nf = 0; nf < 8; nf++) {
        int n0 = nf * 8 + 2 * tg;
        float2 e0 = *(const float2*)(bmr + r0 * 64 + n0);
        float2 e1 = *(const float2*)(bmr + r1 * 64 + n0);
        acc[nf][0] += e0.x; acc[nf][1] += e0.y;
        acc[nf][2] += e1.x; acc[nf][3] += e1.y;
    }

    float m0 = -1e30f, m1 = -1e30f;
#pragma unroll
    for (int nf = 0; nf < 8; nf++) {
        m0 = fmaxf(m0, fmaxf(acc[nf][0], acc[nf][1]));
        m1 = fmaxf(m1, fmaxf(acc[nf][2], acc[nf][3]));
    }
    m0 = fmaxf(m0, __shfl_xor_sync(0xffffffffu, m0, 1));
    m0 = fmaxf(m0, __shfl_xor_sync(0xffffffffu, m0, 2));
    m1 = fmaxf(m1, __shfl_xor_sync(0xffffffffu, m1, 1));
    m1 = fmaxf(m1, __shfl_xor_sync(0xffffffffu, m1, 2));

    float s0 = 0.f, s1 = 0.f;
#pragma unroll
    for (int nf = 0; nf < 8; nf++) {
        acc[nf][0] = __expf(acc[nf][0] - m0); s0 += acc[nf][0];
        acc[nf][1] = __expf(acc[nf][1] - m0); s0 += acc[nf][1];
        acc[nf][2] = __expf(acc[nf][2] - m1); s1 += acc[nf][2];
        acc[nf][3] = __expf(acc[nf][3] - m1); s1 += acc[nf][3];
    }
    s0 += __shfl_xor_sync(0xffffffffu, s0, 1);
    s0 += __shfl_xor_sync(0xffffffffu, s0, 2);
    s1 += __shfl_xor_sync(0xffffffffu, s1, 1);
    s1 += __shfl_xor_sync(0xffffffffu, s1, 2);
    float i0 = 1.f / s0, i1 = 1.f / s1;

#pragma unroll
    for (int nf = 0; nf < 8; nf++) {
        uint2 u;
        split2(acc[nf][0] * i0, acc[nf][1] * i0, u.x, u.y); p2[r0][nf * 4 + tg] = u;
        split2(acc[nf][2] * i1, acc[nf][3] * i1, u.x, u.y); p2[r1][nf * 4 + tg] = u;
    }
    __syncwarp();

    float oacc[4][4];
#pragma unroll
    for (int a = 0; a < 4; a++)
#pragma unroll
        for (int c = 0; c < 4; c++) oacc[a][c] = 0.f;

#pragma unroll
    for (int ks = 0; ks < 4; ks++) {
        int j0 = ks * 8;
        uint32_t ah[4], al[4];
        {
            uint2 t;
            t = p2[mr + g][j0 + tg];          ah[0] = t.x; al[0] = t.y;
            t = p2[mr + g + 8][j0 + tg];      ah[1] = t.x; al[1] = t.y;
            t = p2[mr + g][j0 + tg + 4];      ah[2] = t.x; al[2] = t.y;
            t = p2[mr + g + 8][j0 + tg + 4];  ah[3] = t.x; al[3] = t.y;
        }
#pragma unroll
        for (int nfp = 0; nfp < 2; nfp++) {
            int nf0 = 2 * nfp, nf1 = nf0 + 1;
            int n0 = nf0 * 8 + g;
            uint2 c0 = vt2[n0][j0 + tg],     c1 = vt2[n0][j0 + tg + 4];
            uint2 d0 = vt2[n0 + 8][j0 + tg], d1 = vt2[n0 + 8][j0 + tg + 4];
            mma_bf16(oacc[nf0], ah, c0.x, c1.x);
            mma_bf16(oacc[nf1], ah, d0.x, d1.x);
            mma_bf16(oacc[nf0], ah, c0.y, c1.y);
            mma_bf16(oacc[nf1], ah, d0.y, d1.y);
            mma_bf16(oacc[nf0], al, c0.x, c1.x);
            mma_bf16(oacc[nf1], al, d0.x, d1.x);
        }
    }

    // ctx -> proj operand planes
    int m0r = b * 64 + r0, m1r = b * 64 + r1;
#pragma unroll
    for (int nf = 0; nf < 4; nf++) {
        int dp = h * 16 + nf * 4 + tg;   // pair col 0..127
        int kb = dp >> 4, q = dp & 15;
        uint32_t hi, lo;
        {
            size_t idx = ((size_t)((m0r >> 7) * 8 + kb)) * 2048 + plane_pair(m0r & 127, q);
            split2(oacc[nf][0], oacc[nf][1], hi, lo);
            g_othi[idx] = hi; g_otlo[idx] = lo;
        }
        {
            size_t idx = ((size_t)((m1r >> 7) * 8 + kb)) * 2048 + plane_pair(m1r & 127, q);
            split2(oacc[nf][2], oacc[nf][3], hi, lo);
            g_othi[idx] = hi; g_otlo[idx] = lo;
        }
    }
}

// ---------------------------------------------------------------------------
extern "C" void kernel_launch(void* const* d_in, const int* in_sizes, int n_in,
                              void* d_out, int out_size) {
    (void)in_sizes; (void)n_in; (void)out_size;
    const float* x       = (const float*)d_in[0];
    const float* mask    = (const float*)d_in[1];
    const float* qkv_w   = (const float*)d_in[2];
    const float* qkv_b   = (const float*)d_in[3];
    const float* proj_w  = (const float*)d_in[4];
    const float* proj_b  = (const float*)d_in[5];
    const float* pposw   = (const float*)d_in[6];
    const float* pposb   = (const float*)d_in[7];
    const float* ln1g    = (const float*)d_in[8];
    const float* ln1b    = (const float*)d_in[9];
    const float* fc1w    = (const float*)d_in[10];
    const float* fc1b    = (const float*)d_in[11];
    const float* ln2g    = (const float*)d_in[12];
    const float* ln2b    = (const float*)d_in[13];
    const float* fc2w    = (const float*)d_in[14];
    const float* fc2b    = (const float*)d_in[15];
    const float* ln3g    = (const float*)d_in[16];
    const float* ln3b    = (const float*)d_in[17];
    const float* fc3w    = (const float*)d_in[18];
    const float* fc3b    = (const float*)d_in[19];
    const float* biases  = (const float*)d_in[20];
    const int*   rel_idx = (const int*)d_in[21];
    float* out = (float*)d_out;

    static bool attr_set = false;
    if (!attr_set) {
        cudaFuncSetAttribute(gemm_kernel<0>, cudaFuncAttributeMaxDynamicSharedMemorySize, 98304);
        cudaFuncSetAttribute(gemm_kernel<1>, cudaFuncAttributeMaxDynamicSharedMemorySize, 98304);
        attr_set = true;
    }

    dpb_kernel<<<1, 256>>>(biases, pposw, pposb, ln1g, ln1b, fc1w, fc1b,
                           ln2g, ln2b, fc2w, fc2b, ln3g, ln3b, fc3w, fc3b);
    presplit_kernel<<<100864, 256>>>(x, qkv_w, proj_w);
    bmtab_kernel<<<dim3(NW, HEADS), 256>>>(mask, rel_idx);
    gemm_kernel<0><<<dim3(6, 1568), 256, 98304>>>(qkv_b, nullptr);
    attn_kernel<<<dim3(B_WIN, HEADS), 128>>>();
    gemm_kernel<1><<<dim3(2, 1568), 256, 98304>>>(proj_b, out);
}

// round 8
// speedup vs baseline: 1.7967x; 1.0888x over previous
#include <cuda_runtime.h>
#include <cuda_bf16.h>
#include <cstdint>
#include <math.h>

#define B_WIN   3136
#define NTOK    64
#define DIM     256
#define HEADS   8
#define NW      49
#define LBIAS   225
#define ATT_SCALE 0.17677669529663687f  // 1/sqrt(32)

// ---------------------------------------------------------------------------
// Plane layout (see R7): per (tile128, kchunk32) chunk, 2048 uint32 pairs.
// ---------------------------------------------------------------------------
__device__ uint32_t g_xhi [25690112];
__device__ uint32_t g_xlo [25690112];
__device__ uint32_t g_othi[25690112];
__device__ uint32_t g_otlo[25690112];
__device__ uint32_t g_wqh [98304];
__device__ uint32_t g_wql [98304];
__device__ uint32_t g_wph [32768];
__device__ uint32_t g_wpl [32768];
__device__ uint2    g_q2  [25690112];  // [B_*H][64][16] packed hi/lo
__device__ uint2    g_k2  [25690112];
__device__ float    g_v   [51380224];  // [B_*H][64][32] fp32
__device__ float    g_ptab[LBIAS * HEADS];
__device__ float    g_bm  [1605632];   // bias+mask [49][8][64][64]

// ---------------------------------------------------------------------------
__device__ __forceinline__ void split2(float x, float y, uint32_t& hi, uint32_t& lo) {
    __nv_bfloat162 h = __floats2bfloat162_rn(x, y);
    float hx = __low2float(h), hy = __high2float(h);
    __nv_bfloat162 l = __floats2bfloat162_rn(x - hx, y - hy);
    hi = *reinterpret_cast<uint32_t*>(&h);
    lo = *reinterpret_cast<uint32_t*>(&l);
}

__device__ __forceinline__ uint32_t plane_pair(int r, int q) {
    int j = r >> 1;
    int u = (((r & 1) << 2) | (q >> 2)) ^ (j & 7);
    return (uint32_t)(j * 32 + u * 4 + (q & 3));
}

__device__ __forceinline__ void mma_bf16(float* c, const uint32_t* a, uint32_t b0, uint32_t b1) {
    asm volatile(
        "mma.sync.aligned.m16n8k16.row.col.f32.bf16.bf16.f32 "
        "{%0,%1,%2,%3}, {%4,%5,%6,%7}, {%8,%9}, {%0,%1,%2,%3};\n"
        : "+f"(c[0]), "+f"(c[1]), "+f"(c[2]), "+f"(c[3])
        : "r"(a[0]), "r"(a[1]), "r"(a[2]), "r"(a[3]), "r"(b0), "r"(b1));
}

__device__ __forceinline__ void ldsm4(uint32_t* r, uint32_t a) {
    asm volatile("ldmatrix.sync.aligned.m8n8.x4.shared.b16 {%0,%1,%2,%3}, [%4];"
                 : "=r"(r[0]), "=r"(r[1]), "=r"(r[2]), "=r"(r[3]) : "r"(a));
}

__device__ __forceinline__ void ldgsts16(uint32_t saddr, const void* gp) {
    asm volatile("cp.async.cg.shared.global [%0], [%1], 16;\n" :: "r"(saddr), "l"(gp));
}

// ---------------------------------------------------------------------------
// Kernel 1: DynamicPosBias MLP -> g_ptab[225][8]
// ---------------------------------------------------------------------------
__device__ __forceinline__ void lnrelu16(const float* p, float* t,
                                         const float* gm, const float* bt) {
    float m = 0.f;
#pragma unroll
    for (int j = 0; j < 16; j++) m += p[j];
    m *= (1.f / 16.f);
    float v = 0.f;
#pragma unroll
    for (int j = 0; j < 16; j++) { float d = p[j] - m; v += d * d; }
    v *= (1.f / 16.f);
    float is = rsqrtf(v + 1e-5f);
#pragma unroll
    for (int j = 0; j < 16; j++) {
        float u = (p[j] - m) * is * gm[j] + bt[j];
        t[j] = u > 0.f ? u : 0.f;
    }
}

__global__ void dpb_kernel(const float* __restrict__ biases,
                           const float* __restrict__ pw, const float* __restrict__ pb,
                           const float* __restrict__ g1, const float* __restrict__ b1,
                           const float* __restrict__ w1, const float* __restrict__ c1,
                           const float* __restrict__ g2, const float* __restrict__ b2,
                           const float* __restrict__ w2, const float* __restrict__ c2,
                           const float* __restrict__ g3, const float* __restrict__ b3,
                           const float* __restrict__ w3, const float* __restrict__ c3) {
    int r = threadIdx.x;
    if (r >= LBIAS) return;
    float p[16], t[16];
    float x0 = biases[2 * r], x1 = biases[2 * r + 1];
#pragma unroll
    for (int j = 0; j < 16; j++) p[j] = x0 * pw[2 * j] + x1 * pw[2 * j + 1] + pb[j];
    lnrelu16(p, t, g1, b1);
#pragma unroll
    for (int o = 0; o < 16; o++) {
        float s = c1[o];
#pragma unroll
        for (int j = 0; j < 16; j++) s += t[j] * w1[o * 16 + j];
        p[o] = s;
    }
    lnrelu16(p, t, g2, b2);
#pragma unroll
    for (int o = 0; o < 16; o++) {
        float s = c2[o];
#pragma unroll
        for (int j = 0; j < 16; j++) s += t[j] * w2[o * 16 + j];
        p[o] = s;
    }
    lnrelu16(p, t, g3, b3);
#pragma unroll
    for (int o = 0; o < 8; o++) {
        float s = c3[o];
#pragma unroll
        for (int j = 0; j < 16; j++) s += t[j] * w3[o * 16 + j];
        g_ptab[r * 8 + o] = s;
    }
}

// ---------------------------------------------------------------------------
// Kernel 1b: pre-split x / qkv_w / proj_w into plane chunks
// ---------------------------------------------------------------------------
__global__ void presplit_kernel(const float* __restrict__ x,
                                const float* __restrict__ qw,
                                const float* __restrict__ pw) {
    long i = (long)blockIdx.x * 256 + threadIdx.x;
    const float2* src; uint32_t *dh, *dl; long j;
    if (i < 25690112L) { j = i; src = (const float2*)x; dh = g_xhi; dl = g_xlo; }
    else if (i < 25690112L + 98304) { j = i - 25690112L; src = (const float2*)qw; dh = g_wqh; dl = g_wql; }
    else if (i < 25690112L + 98304 + 32768) { j = i - 25690112L - 98304; src = (const float2*)pw; dh = g_wph; dl = g_wpl; }
    else return;
    int m = (int)(j >> 7);
    int pc = (int)(j & 127);
    int tile = m >> 7, r = m & 127;
    int kb = pc >> 4, q = pc & 15;
    long idx = ((long)(tile * 8 + kb)) * 2048 + plane_pair(r, q);
    float2 f = src[j];
    uint32_t hi, lo;
    split2(f.x, f.y, hi, lo);
    dh[idx] = hi;
    dl[idx] = lo;
}

// ---------------------------------------------------------------------------
// Kernel 1c: combined bias+mask table
// ---------------------------------------------------------------------------
__global__ void bmtab_kernel(const float* __restrict__ mask,
                             const int* __restrict__ rel_idx) {
    int wb = blockIdx.x, h = blockIdx.y;
    float* dst = g_bm + (size_t)(wb * 8 + h) * 4096;
    const float* msk = mask + (size_t)wb * 4096;
    for (int i = threadIdx.x; i < 4096; i += blockDim.x)
        dst[i] = g_ptab[rel_idx[i] * 8 + h] + msk[i];
}

// ---------------------------------------------------------------------------
// Kernel 2/4: HMMA GEMM (unchanged from R7 win).
// ---------------------------------------------------------------------------
template <int MODE>
__global__ __launch_bounds__(256, 2) void gemm_kernel(const float* __restrict__ bias,
                                                      float* __restrict__ Out) {
    extern __shared__ char smem[];
    uint32_t sb = (uint32_t)__cvta_generic_to_shared(smem);

    int bm = blockIdx.y, bn = blockIdx.x;
    int tid = threadIdx.x;
    int warp = tid >> 5, lane = tid & 31;
    int wm = warp >> 1, wn = warp & 1;
    int g = lane >> 2, tg = lane & 3;

    const uint32_t* Ah = MODE ? g_othi : g_xhi;
    const uint32_t* Al = MODE ? g_otlo : g_xlo;
    const uint32_t* Bh = MODE ? g_wph : g_wqh;
    const uint32_t* Bl = MODE ? g_wpl : g_wql;

    float acc[2][8][4];
#pragma unroll
    for (int a = 0; a < 2; a++)
#pragma unroll
        for (int b = 0; b < 8; b++)
#pragma unroll
            for (int c = 0; c < 4; c++) acc[a][b][c] = 0.f;

    auto mkbase = [&](int r, int lb) {
        int j = r >> 1, a = (r & 1) << 2;
        return (uint32_t)(j * 128 + (((a ^ lb) ^ (j & 7)) << 4));
    };
    int rA = lane & 15, lbA = lane >> 4;
    uint32_t baseA0 = mkbase(wm * 32 + rA, lbA);
    uint32_t baseA1 = mkbase(wm * 32 + 16 + rA, lbA);
    int rB = (lane & 7) | ((lane >> 1) & 8);
    int lbB = (lane >> 3) & 1;
    uint32_t baseB[4];
#pragma unroll
    for (int i = 0; i < 4; i++) baseB[i] = mkbase(wn * 64 + i * 16 + rB, lbB);

    auto issue = [&](int kb, int s) {
        uint32_t S = sb + (uint32_t)s * 32768;
        const uint32_t* srcs[4] = {
            Ah + (size_t)(bm * 8 + kb) * 2048, Al + (size_t)(bm * 8 + kb) * 2048,
            Bh + (size_t)(bn * 8 + kb) * 2048, Bl + (size_t)(bn * 8 + kb) * 2048 };
#pragma unroll
        for (int p = 0; p < 4; p++) {
#pragma unroll
            for (int e = 0; e < 2; e++) {
                int u = tid + e * 256;
                ldgsts16(S + (uint32_t)p * 8192 + u * 16, srcs[p] + u * 4);
            }
        }
        asm volatile("cp.async.commit_group;\n" ::: "memory");
    };

    issue(0, 0);
    issue(1, 1);

    for (int kb = 0; kb < 8; kb++) {
        int s = kb % 3;
        if (kb < 7) asm volatile("cp.async.wait_group 1;\n" ::: "memory");
        else        asm volatile("cp.async.wait_group 0;\n" ::: "memory");
        __syncthreads();

        uint32_t S = sb + (uint32_t)s * 32768;
#pragma unroll
        for (int ks = 0; ks < 2; ks++) {
            uint32_t uo = ks * 32;
            uint32_t ah0[4], ah1[4], al0[4], al1[4];
            ldsm4(ah0, S + (baseA0 ^ uo));
            ldsm4(ah1, S + (baseA1 ^ uo));
            ldsm4(al0, S + 8192 + (baseA0 ^ uo));
            ldsm4(al1, S + 8192 + (baseA1 ^ uo));
#pragma unroll
            for (int nfp = 0; nfp < 4; nfp++) {
                int nf0 = 2 * nfp, nf1 = nf0 + 1;
                uint32_t bh[4], bl[4];
                ldsm4(bh, S + 16384 + (baseB[nfp] ^ uo));
                ldsm4(bl, S + 24576 + (baseB[nfp] ^ uo));
                mma_bf16(acc[0][nf0], ah0, bh[0], bh[1]);
                mma_bf16(acc[1][nf0], ah1, bh[0], bh[1]);
                mma_bf16(acc[0][nf1], ah0, bh[2], bh[3]);
                mma_bf16(acc[1][nf1], ah1, bh[2], bh[3]);
                mma_bf16(acc[0][nf0], ah0, bl[0], bl[1]);
                mma_bf16(acc[1][nf0], ah1, bl[0], bl[1]);
                mma_bf16(acc[0][nf1], ah0, bl[2], bl[3]);
                mma_bf16(acc[1][nf1], ah1, bl[2], bl[3]);
                mma_bf16(acc[0][nf0], al0, bh[0], bh[1]);
                mma_bf16(acc[1][nf0], al1, bh[0], bh[1]);
                mma_bf16(acc[0][nf1], al0, bh[2], bh[3]);
                mma_bf16(acc[1][nf1], al1, bh[2], bh[3]);
            }
        }
        if (kb < 6) issue(kb + 2, (kb + 2) % 3);
    }

    int obase = bn * 128 + wn * 64;
#pragma unroll
    for (int nf = 0; nf < 8; nf++) {
        int o = obase + nf * 8 + 2 * tg;
        float bb0 = bias[o], bb1 = bias[o + 1];
#pragma unroll
        for (int mf = 0; mf < 2; mf++) {
#pragma unroll
            for (int r2 = 0; r2 < 2; r2++) {
                int m = bm * 128 + wm * 32 + mf * 16 + g + r2 * 8;
                float v0 = acc[mf][nf][r2 * 2] + bb0;
                float v1 = acc[mf][nf][r2 * 2 + 1] + bb1;
                if (MODE == 1) {
                    *(float2*)(Out + (size_t)m * 256 + o) = make_float2(v0, v1);
                } else {
                    int s = o >> 8, hh = (o >> 5) & 7, d = o & 31;
                    int bw = m >> 6, n = m & 63;
                    size_t di = ((size_t)(bw * 8 + hh) * 64 + n) * 16 + (d >> 1);
                    if (s == 0)      { uint2 u; split2(v0 * ATT_SCALE, v1 * ATT_SCALE, u.x, u.y); g_q2[di] = u; }
                    else if (s == 1) { uint2 u; split2(v0, v1, u.x, u.y); g_k2[di] = u; }
                    else             { *(float2*)(g_v + (di << 1)) = make_float2(v0, v1); }
                }
            }
        }
    }
}

// ---------------------------------------------------------------------------
// Kernel 3: attention per (window b, head h). 4 warps, 16 query rows each.
// q direct from gmem; k via cp.async; probs stay in registers (acc layout IS
// the P.V a-fragment layout); ctx -> proj operand planes. smem 19KB.
// ---------------------------------------------------------------------------
__global__ __launch_bounds__(128, 5) void attn_kernel() {
    __shared__ uint2 k2s[64][20];
    __shared__ uint2 vt2[32][36];   // V^T: [d][token-pair]

    int b = blockIdx.x, h = blockIdx.y;
    int tid = threadIdx.x;
    int warp = tid >> 5, lane = tid & 31;
    int g = lane >> 2, tg = lane & 3;
    int mr = warp * 16;

    const uint2* qg = g_q2 + (size_t)(b * 8 + h) * 1024;
    const uint2* kg = g_k2 + (size_t)(b * 8 + h) * 1024;
    const float* vg = g_v  + (size_t)(b * 8 + h) * 2048;

    // k tile: cp.async 16B units (4 per thread), in flight during v/q loads
#pragma unroll
    for (int e = 0; e < 4; e++) {
        int it = tid + e * 128;          // 0..511
        int t = it >> 3, j = (it & 7) * 2;
        ldgsts16((uint32_t)__cvta_generic_to_shared(&k2s[t][j]), kg + t * 16 + j);
    }
    asm volatile("cp.async.commit_group;\n" ::: "memory");

    // v: fp32 -> split -> V^T smem
    for (int it = tid; it < 1024; it += 128) {
        int d = it & 31, j = it >> 5;
        uint2 u;
        split2(vg[(2 * j) * 32 + d], vg[(2 * j + 1) * 32 + d], u.x, u.y);
        vt2[d][j] = u;
    }

    // q fragments straight from gmem
    uint32_t qh_[2][4], ql_[2][4];
#pragma unroll
    for (int ks = 0; ks < 2; ks++) {
        int j0 = ks * 8;
        uint2 t;
        t = qg[(mr + g) * 16 + j0 + tg];          qh_[ks][0] = t.x; ql_[ks][0] = t.y;
        t = qg[(mr + g + 8) * 16 + j0 + tg];      qh_[ks][1] = t.x; ql_[ks][1] = t.y;
        t = qg[(mr + g) * 16 + j0 + tg + 4];      qh_[ks][2] = t.x; ql_[ks][2] = t.y;
        t = qg[(mr + g + 8) * 16 + j0 + tg + 4];  qh_[ks][3] = t.x; ql_[ks][3] = t.y;
    }

    asm volatile("cp.async.wait_group 0;\n" ::: "memory");
    __syncthreads();

    // logits = q @ k^T  (q pre-scaled)
    float acc[8][4];
#pragma unroll
    for (int a = 0; a < 8; a++)
#pragma unroll
        for (int c = 0; c < 4; c++) acc[a][c] = 0.f;

#pragma unroll
    for (int ks = 0; ks < 2; ks++) {
        int j0 = ks * 8;
#pragma unroll
        for (int nfp = 0; nfp < 4; nfp++) {
            int nf0 = 2 * nfp, nf1 = nf0 + 1;
            int n0 = nf0 * 8 + g;
            uint2 c0 = k2s[n0][j0 + tg],     c1 = k2s[n0][j0 + tg + 4];
            uint2 d0 = k2s[n0 + 8][j0 + tg], d1 = k2s[n0 + 8][j0 + tg + 4];
            mma_bf16(acc[nf0], qh_[ks], c0.x, c1.x);
            mma_bf16(acc[nf1], qh_[ks], d0.x, d1.x);
            mma_bf16(acc[nf0], qh_[ks], c0.y, c1.y);
            mma_bf16(acc[nf1], qh_[ks], d0.y, d1.y);
            mma_bf16(acc[nf0], ql_[ks], c0.x, c1.x);
            mma_bf16(acc[nf1], ql_[ks], d0.x, d1.x);
        }
    }

    // combined bias+mask
    int r0 = mr + g, r1 = r0 + 8;
    const float* bmr = g_bm + (size_t)((b % NW) * 8 + h) * 4096;
#pragma unroll
    for (int nf = 0; nf < 8; nf++) {
        int n0 = nf * 8 + 2 * tg;
        float2 e0 = *(const float2*)(bmr + r0 * 64 + n0);
        float2 e1 = *(const float2*)(bmr + r1 * 64 + n0);
        acc[nf][0] += e0.x; acc[nf][1] += e0.y;
        acc[nf][2] += e1.x; acc[nf][3] += e1.y;
    }

    // softmax across the quad (rows r0, r1)
    float m0 = -1e30f, m1 = -1e30f;
#pragma unroll
    for (int nf = 0; nf < 8; nf++) {
        m0 = fmaxf(m0, fmaxf(acc[nf][0], acc[nf][1]));
        m1 = fmaxf(m1, fmaxf(acc[nf][2], acc[nf][3]));
    }
    m0 = fmaxf(m0, __shfl_xor_sync(0xffffffffu, m0, 1));
    m0 = fmaxf(m0, __shfl_xor_sync(0xffffffffu, m0, 2));
    m1 = fmaxf(m1, __shfl_xor_sync(0xffffffffu, m1, 1));
    m1 = fmaxf(m1, __shfl_xor_sync(0xffffffffu, m1, 2));

    float s0 = 0.f, s1 = 0.f;
#pragma unroll
    for (int nf = 0; nf < 8; nf++) {
        acc[nf][0] = __expf(acc[nf][0] - m0); s0 += acc[nf][0];
        acc[nf][1] = __expf(acc[nf][1] - m0); s0 += acc[nf][1];
        acc[nf][2] = __expf(acc[nf][2] - m1); s1 += acc[nf][2];
        acc[nf][3] = __expf(acc[nf][3] - m1); s1 += acc[nf][3];
    }
    s0 += __shfl_xor_sync(0xffffffffu, s0, 1);
    s0 += __shfl_xor_sync(0xffffffffu, s0, 2);
    s1 += __shfl_xor_sync(0xffffffffu, s1, 1);
    s1 += __shfl_xor_sync(0xffffffffu, s1, 2);
    float i0 = 1.f / s0, i1 = 1.f / s1;

    // out = P @ V  — P a-fragments come straight from acc (lane-local!)
    float oacc[4][4];
#pragma unroll
    for (int a = 0; a < 4; a++)
#pragma unroll
        for (int c = 0; c < 4; c++) oacc[a][c] = 0.f;

#pragma unroll
    for (int ks = 0; ks < 4; ks++) {
        uint32_t ah[4], al[4];
        split2(acc[2 * ks][0] * i0,     acc[2 * ks][1] * i0,     ah[0], al[0]);
        split2(acc[2 * ks][2] * i1,     acc[2 * ks][3] * i1,     ah[1], al[1]);
        split2(acc[2 * ks + 1][0] * i0, acc[2 * ks + 1][1] * i0, ah[2], al[2]);
        split2(acc[2 * ks + 1][2] * i1, acc[2 * ks + 1][3] * i1, ah[3], al[3]);
        int j0 = ks * 8;
#pragma unroll
        for (int nfp = 0; nfp < 2; nfp++) {
            int nf0 = 2 * nfp, nf1 = nf0 + 1;
            int n0 = nf0 * 8 + g;
            uint2 c0 = vt2[n0][j0 + tg],     c1 = vt2[n0][j0 + tg + 4];
            uint2 d0 = vt2[n0 + 8][j0 + tg], d1 = vt2[n0 + 8][j0 + tg + 4];
            mma_bf16(oacc[nf0], ah, c0.x, c1.x);
            mma_bf16(oacc[nf1], ah, d0.x, d1.x);
            mma_bf16(oacc[nf0], ah, c0.y, c1.y);
            mma_bf16(oacc[nf1], ah, d0.y, d1.y);
            mma_bf16(oacc[nf0], al, c0.x, c1.x);
            mma_bf16(oacc[nf1], al, d0.x, d1.x);
        }
    }

    // ctx -> proj operand planes
    int m0r = b * 64 + r0, m1r = b * 64 + r1;
#pragma unroll
    for (int nf = 0; nf < 4; nf++) {
        int dp = h * 16 + nf * 4 + tg;
        int kb = dp >> 4, q = dp & 15;
        uint32_t hi, lo;
        {
            size_t idx = ((size_t)((m0r >> 7) * 8 + kb)) * 2048 + plane_pair(m0r & 127, q);
            split2(oacc[nf][0], oacc[nf][1], hi, lo);
            g_othi[idx] = hi; g_otlo[idx] = lo;
        }
        {
            size_t idx = ((size_t)((m1r >> 7) * 8 + kb)) * 2048 + plane_pair(m1r & 127, q);
            split2(oacc[nf][2], oacc[nf][3], hi, lo);
            g_othi[idx] = hi; g_otlo[idx] = lo;
        }
    }
}

// ---------------------------------------------------------------------------
extern "C" void kernel_launch(void* const* d_in, const int* in_sizes, int n_in,
                              void* d_out, int out_size) {
    (void)in_sizes; (void)n_in; (void)out_size;
    const float* x       = (const float*)d_in[0];
    const float* mask    = (const float*)d_in[1];
    const float* qkv_w   = (const float*)d_in[2];
    const float* qkv_b   = (const float*)d_in[3];
    const float* proj_w  = (const float*)d_in[4];
    const float* proj_b  = (const float*)d_in[5];
    const float* pposw   = (const float*)d_in[6];
    const float* pposb   = (const float*)d_in[7];
    const float* ln1g    = (const float*)d_in[8];
    const float* ln1b    = (const float*)d_in[9];
    const float* fc1w    = (const float*)d_in[10];
    const float* fc1b    = (const float*)d_in[11];
    const float* ln2g    = (const float*)d_in[12];
    const float* ln2b    = (const float*)d_in[13];
    const float* fc2w    = (const float*)d_in[14];
    const float* fc2b    = (const float*)d_in[15];
    const float* ln3g    = (const float*)d_in[16];
    const float* ln3b    = (const float*)d_in[17];
    const float* fc3w    = (const float*)d_in[18];
    const float* fc3b    = (const float*)d_in[19];
    const float* biases  = (const float*)d_in[20];
    const int*   rel_idx = (const int*)d_in[21];
    float* out = (float*)d_out;

    static bool attr_set = false;
    if (!attr_set) {
        cudaFuncSetAttribute(gemm_kernel<0>, cudaFuncAttributeMaxDynamicSharedMemorySize, 98304);
        cudaFuncSetAttribute(gemm_kernel<1>, cudaFuncAttributeMaxDynamicSharedMemorySize, 98304);
        attr_set = true;
    }

    dpb_kernel<<<1, 256>>>(biases, pposw, pposb, ln1g, ln1b, fc1w, fc1b,
                           ln2g, ln2b, fc2w, fc2b, ln3g, ln3b, fc3w, fc3b);
    presplit_kernel<<<100864, 256>>>(x, qkv_w, proj_w);
    bmtab_kernel<<<dim3(NW, HEADS), 256>>>(mask, rel_idx);
    gemm_kernel<0><<<dim3(6, 1568), 256, 98304>>>(qkv_b, nullptr);
    attn_kernel<<<dim3(B_WIN, HEADS), 128>>>();
    gemm_kernel<1><<<dim3(2, 1568), 256, 98304>>>(proj_b, out);
}

// round 9
// speedup vs baseline: 1.8510x; 1.0302x over previous
#include <cuda_runtime.h>
#include <cuda_bf16.h>
#include <cstdint>
#include <math.h>

#define B_WIN   3136
#define NTOK    64
#define DIM     256
#define HEADS   8
#define NW      49
#define LBIAS   225
#define ATT_SCALE 0.17677669529663687f  // 1/sqrt(32)

// ---------------------------------------------------------------------------
// Plane layout (see R7): per (tile128, kchunk32) chunk, 2048 uint32 pairs.
// ---------------------------------------------------------------------------
__device__ uint32_t g_xhi [25690112];
__device__ uint32_t g_xlo [25690112];
__device__ uint32_t g_othi[25690112];
__device__ uint32_t g_otlo[25690112];
__device__ uint32_t g_wqh [98304];
__device__ uint32_t g_wql [98304];
__device__ uint32_t g_wph [32768];
__device__ uint32_t g_wpl [32768];
__device__ uint2    g_q2  [25690112];  // [B_*H][64][16] packed hi/lo
__device__ uint2    g_k2  [25690112];
__device__ float    g_v   [51380224];  // [B_*H][64][32] fp32
__device__ float    g_ptab[LBIAS * HEADS];
__device__ float    g_bm  [1605632];   // bias+mask [49][8][64][64]

// ---------------------------------------------------------------------------
__device__ __forceinline__ void split2(float x, float y, uint32_t& hi, uint32_t& lo) {
    __nv_bfloat162 h = __floats2bfloat162_rn(x, y);
    float hx = __low2float(h), hy = __high2float(h);
    __nv_bfloat162 l = __floats2bfloat162_rn(x - hx, y - hy);
    hi = *reinterpret_cast<uint32_t*>(&h);
    lo = *reinterpret_cast<uint32_t*>(&l);
}

__device__ __forceinline__ uint32_t plane_pair(int r, int q) {
    int j = r >> 1;
    int u = (((r & 1) << 2) | (q >> 2)) ^ (j & 7);
    return (uint32_t)(j * 32 + u * 4 + (q & 3));
}

__device__ __forceinline__ void mma_bf16(float* c, const uint32_t* a, uint32_t b0, uint32_t b1) {
    asm volatile(
        "mma.sync.aligned.m16n8k16.row.col.f32.bf16.bf16.f32 "
        "{%0,%1,%2,%3}, {%4,%5,%6,%7}, {%8,%9}, {%0,%1,%2,%3};\n"
        : "+f"(c[0]), "+f"(c[1]), "+f"(c[2]), "+f"(c[3])
        : "r"(a[0]), "r"(a[1]), "r"(a[2]), "r"(a[3]), "r"(b0), "r"(b1));
}

__device__ __forceinline__ void ldsm4(uint32_t* r, uint32_t a) {
    asm volatile("ldmatrix.sync.aligned.m8n8.x4.shared.b16 {%0,%1,%2,%3}, [%4];"
                 : "=r"(r[0]), "=r"(r[1]), "=r"(r[2]), "=r"(r[3]) : "r"(a));
}

__device__ __forceinline__ void ldgsts16(uint32_t saddr, const void* gp) {
    asm volatile("cp.async.cg.shared.global [%0], [%1], 16;\n" :: "r"(saddr), "l"(gp));
}

// ---------------------------------------------------------------------------
// Kernel 1: DynamicPosBias MLP -> g_ptab[225][8]
// ---------------------------------------------------------------------------
__device__ __forceinline__ void lnrelu16(const float* p, float* t,
                                         const float* gm, const float* bt) {
    float m = 0.f;
#pragma unroll
    for (int j = 0; j < 16; j++) m += p[j];
    m *= (1.f / 16.f);
    float v = 0.f;
#pragma unroll
    for (int j = 0; j < 16; j++) { float d = p[j] - m; v += d * d; }
    v *= (1.f / 16.f);
    float is = rsqrtf(v + 1e-5f);
#pragma unroll
    for (int j = 0; j < 16; j++) {
        float u = (p[j] - m) * is * gm[j] + bt[j];
        t[j] = u > 0.f ? u : 0.f;
    }
}

__global__ void dpb_kernel(const float* __restrict__ biases,
                           const float* __restrict__ pw, const float* __restrict__ pb,
                           const float* __restrict__ g1, const float* __restrict__ b1,
                           const float* __restrict__ w1, const float* __restrict__ c1,
                           const float* __restrict__ g2, const float* __restrict__ b2,
                           const float* __restrict__ w2, const float* __restrict__ c2,
                           const float* __restrict__ g3, const float* __restrict__ b3,
                           const float* __restrict__ w3, const float* __restrict__ c3) {
    int r = threadIdx.x;
    if (r >= LBIAS) return;
    float p[16], t[16];
    float x0 = biases[2 * r], x1 = biases[2 * r + 1];
#pragma unroll
    for (int j = 0; j < 16; j++) p[j] = x0 * pw[2 * j] + x1 * pw[2 * j + 1] + pb[j];
    lnrelu16(p, t, g1, b1);
#pragma unroll
    for (int o = 0; o < 16; o++) {
        float s = c1[o];
#pragma unroll
        for (int j = 0; j < 16; j++) s += t[j] * w1[o * 16 + j];
        p[o] = s;
    }
    lnrelu16(p, t, g2, b2);
#pragma unroll
    for (int o = 0; o < 16; o++) {
        float s = c2[o];
#pragma unroll
        for (int j = 0; j < 16; j++) s += t[j] * w2[o * 16 + j];
        p[o] = s;
    }
    lnrelu16(p, t, g3, b3);
#pragma unroll
    for (int o = 0; o < 8; o++) {
        float s = c3[o];
#pragma unroll
        for (int j = 0; j < 16; j++) s += t[j] * w3[o * 16 + j];
        g_ptab[r * 8 + o] = s;
    }
}

// ---------------------------------------------------------------------------
// Kernel 1b: pre-split x / qkv_w / proj_w into plane chunks
// ---------------------------------------------------------------------------
__global__ void presplit_kernel(const float* __restrict__ x,
                                const float* __restrict__ qw,
                                const float* __restrict__ pw) {
    long i = (long)blockIdx.x * 256 + threadIdx.x;
    const float2* src; uint32_t *dh, *dl; long j;
    if (i < 25690112L) { j = i; src = (const float2*)x; dh = g_xhi; dl = g_xlo; }
    else if (i < 25690112L + 98304) { j = i - 25690112L; src = (const float2*)qw; dh = g_wqh; dl = g_wql; }
    else if (i < 25690112L + 98304 + 32768) { j = i - 25690112L - 98304; src = (const float2*)pw; dh = g_wph; dl = g_wpl; }
    else return;
    int m = (int)(j >> 7);
    int pc = (int)(j & 127);
    int tile = m >> 7, r = m & 127;
    int kb = pc >> 4, q = pc & 15;
    long idx = ((long)(tile * 8 + kb)) * 2048 + plane_pair(r, q);
    float2 f = src[j];
    uint32_t hi, lo;
    split2(f.x, f.y, hi, lo);
    dh[idx] = hi;
    dl[idx] = lo;
}

// ---------------------------------------------------------------------------
// Kernel 1c: combined bias+mask table
// ---------------------------------------------------------------------------
__global__ void bmtab_kernel(const float* __restrict__ mask,
                             const int* __restrict__ rel_idx) {
    int wb = blockIdx.x, h = blockIdx.y;
    float* dst = g_bm + (size_t)(wb * 8 + h) * 4096;
    const float* msk = mask + (size_t)wb * 4096;
    for (int i = threadIdx.x; i < 4096; i += blockDim.x)
        dst[i] = g_ptab[rel_idx[i] * 8 + h] + msk[i];
}

// ---------------------------------------------------------------------------
// Kernel 2/4: HMMA GEMM, BM=BN=128, K=256 in 8 chunks of 32.
// B fragments double-buffered (prefetch nfp+1 during nfp's mma); cp.async
// refill hoisted before the mma loop.
// ---------------------------------------------------------------------------
template <int MODE>
__global__ __launch_bounds__(256, 2) void gemm_kernel(const float* __restrict__ bias,
                                                      float* __restrict__ Out) {
    extern __shared__ char smem[];
    uint32_t sb = (uint32_t)__cvta_generic_to_shared(smem);

    int bm = blockIdx.y, bn = blockIdx.x;
    int tid = threadIdx.x;
    int warp = tid >> 5, lane = tid & 31;
    int wm = warp >> 1, wn = warp & 1;
    int g = lane >> 2, tg = lane & 3;

    const uint32_t* Ah = MODE ? g_othi : g_xhi;
    const uint32_t* Al = MODE ? g_otlo : g_xlo;
    const uint32_t* Bh = MODE ? g_wph : g_wqh;
    const uint32_t* Bl = MODE ? g_wpl : g_wql;

    float acc[2][8][4];
#pragma unroll
    for (int a = 0; a < 2; a++)
#pragma unroll
        for (int b = 0; b < 8; b++)
#pragma unroll
            for (int c = 0; c < 4; c++) acc[a][b][c] = 0.f;

    auto mkbase = [&](int r, int lb) {
        int j = r >> 1, a = (r & 1) << 2;
        return (uint32_t)(j * 128 + (((a ^ lb) ^ (j & 7)) << 4));
    };
    int rA = lane & 15, lbA = lane >> 4;
    uint32_t baseA0 = mkbase(wm * 32 + rA, lbA);
    uint32_t baseA1 = mkbase(wm * 32 + 16 + rA, lbA);
    int rB = (lane & 7) | ((lane >> 1) & 8);
    int lbB = (lane >> 3) & 1;
    uint32_t baseB[4];
#pragma unroll
    for (int i = 0; i < 4; i++) baseB[i] = mkbase(wn * 64 + i * 16 + rB, lbB);

    auto issue = [&](int kb, int s) {
        uint32_t S = sb + (uint32_t)s * 32768;
        const uint32_t* srcs[4] = {
            Ah + (size_t)(bm * 8 + kb) * 2048, Al + (size_t)(bm * 8 + kb) * 2048,
            Bh + (size_t)(bn * 8 + kb) * 2048, Bl + (size_t)(bn * 8 + kb) * 2048 };
#pragma unroll
        for (int p = 0; p < 4; p++) {
#pragma unroll
            for (int e = 0; e < 2; e++) {
                int u = tid + e * 256;
                ldgsts16(S + (uint32_t)p * 8192 + u * 16, srcs[p] + u * 4);
            }
        }
        asm volatile("cp.async.commit_group;\n" ::: "memory");
    };

    issue(0, 0);
    issue(1, 1);

    for (int kb = 0; kb < 8; kb++) {
        int s = kb % 3;
        if (kb < 7) asm volatile("cp.async.wait_group 1;\n" ::: "memory");
        else        asm volatile("cp.async.wait_group 0;\n" ::: "memory");
        __syncthreads();
        if (kb < 6) issue(kb + 2, (kb + 2) % 3);  // overlap refill with mma

        uint32_t S = sb + (uint32_t)s * 32768;
#pragma unroll
        for (int ks = 0; ks < 2; ks++) {
            uint32_t uo = ks * 32;
            uint32_t ah0[4], ah1[4], al0[4], al1[4];
            ldsm4(ah0, S + (baseA0 ^ uo));
            ldsm4(ah1, S + (baseA1 ^ uo));
            ldsm4(al0, S + 8192 + (baseA0 ^ uo));
            ldsm4(al1, S + 8192 + (baseA1 ^ uo));
            uint32_t bhA[4], blA[4], bhB[4], blB[4];
            ldsm4(bhA, S + 16384 + (baseB[0] ^ uo));
            ldsm4(blA, S + 24576 + (baseB[0] ^ uo));
#pragma unroll
            for (int nfp = 0; nfp < 4; nfp++) {
                uint32_t (&bh)[4]  = (nfp & 1) ? bhB : bhA;
                uint32_t (&bl)[4]  = (nfp & 1) ? blB : blA;
                uint32_t (&nbh)[4] = (nfp & 1) ? bhA : bhB;
                uint32_t (&nbl)[4] = (nfp & 1) ? blA : blB;
                if (nfp < 3) {
                    ldsm4(nbh, S + 16384 + (baseB[nfp + 1] ^ uo));
                    ldsm4(nbl, S + 24576 + (baseB[nfp + 1] ^ uo));
                }
                int nf0 = 2 * nfp, nf1 = nf0 + 1;
                mma_bf16(acc[0][nf0], ah0, bh[0], bh[1]);
                mma_bf16(acc[1][nf0], ah1, bh[0], bh[1]);
                mma_bf16(acc[0][nf1], ah0, bh[2], bh[3]);
                mma_bf16(acc[1][nf1], ah1, bh[2], bh[3]);
                mma_bf16(acc[0][nf0], ah0, bl[0], bl[1]);
                mma_bf16(acc[1][nf0], ah1, bl[0], bl[1]);
                mma_bf16(acc[0][nf1], ah0, bl[2], bl[3]);
                mma_bf16(acc[1][nf1], ah1, bl[2], bl[3]);
                mma_bf16(acc[0][nf0], al0, bh[0], bh[1]);
                mma_bf16(acc[1][nf0], al1, bh[0], bh[1]);
                mma_bf16(acc[0][nf1], al0, bh[2], bh[3]);
                mma_bf16(acc[1][nf1], al1, bh[2], bh[3]);
            }
        }
    }

    int obase = bn * 128 + wn * 64;
#pragma unroll
    for (int nf = 0; nf < 8; nf++) {
        int o = obase + nf * 8 + 2 * tg;
        float bb0 = bias[o], bb1 = bias[o + 1];
#pragma unroll
        for (int mf = 0; mf < 2; mf++) {
#pragma unroll
            for (int r2 = 0; r2 < 2; r2++) {
                int m = bm * 128 + wm * 32 + mf * 16 + g + r2 * 8;
                float v0 = acc[mf][nf][r2 * 2] + bb0;
                float v1 = acc[mf][nf][r2 * 2 + 1] + bb1;
                if (MODE == 1) {
                    *(float2*)(Out + (size_t)m * 256 + o) = make_float2(v0, v1);
                } else {
                    int s = o >> 8, hh = (o >> 5) & 7, d = o & 31;
                    int bw = m >> 6, n = m & 63;
                    size_t di = ((size_t)(bw * 8 + hh) * 64 + n) * 16 + (d >> 1);
                    if (s == 0)      { uint2 u; split2(v0 * ATT_SCALE, v1 * ATT_SCALE, u.x, u.y); g_q2[di] = u; }
                    else if (s == 1) { uint2 u; split2(v0, v1, u.x, u.y); g_k2[di] = u; }
                    else             { *(float2*)(g_v + (di << 1)) = make_float2(v0, v1); }
                }
            }
        }
    }
}

// ---------------------------------------------------------------------------
// Kernel 3: attention per (window b, head h). 4 warps, 16 query rows each.
// ---------------------------------------------------------------------------
__global__ __launch_bounds__(128, 6) void attn_kernel() {
    __shared__ uint2 k2s[64][20];
    __shared__ uint2 vt2[32][36];   // V^T: [d][token-pair]

    int b = blockIdx.x, h = blockIdx.y;
    int tid = threadIdx.x;
    int warp = tid >> 5, lane = tid & 31;
    int g = lane >> 2, tg = lane & 3;
    int mr = warp * 16;

    const uint2* qg = g_q2 + (size_t)(b * 8 + h) * 1024;
    const uint2* kg = g_k2 + (size_t)(b * 8 + h) * 1024;
    const float* vg = g_v  + (size_t)(b * 8 + h) * 2048;

    // k tile via cp.async
#pragma unroll
    for (int e = 0; e < 4; e++) {
        int it = tid + e * 128;
        int t = it >> 3, j = (it & 7) * 2;
        ldgsts16((uint32_t)__cvta_generic_to_shared(&k2s[t][j]), kg + t * 16 + j);
    }
    asm volatile("cp.async.commit_group;\n" ::: "memory");

    // v: fp32 -> split -> V^T smem
    for (int it = tid; it < 1024; it += 128) {
        int d = it & 31, j = it >> 5;
        uint2 u;
        split2(vg[(2 * j) * 32 + d], vg[(2 * j + 1) * 32 + d], u.x, u.y);
        vt2[d][j] = u;
    }

    // q fragments straight from gmem
    uint32_t qh_[2][4], ql_[2][4];
#pragma unroll
    for (int ks = 0; ks < 2; ks++) {
        int j0 = ks * 8;
        uint2 t;
        t = qg[(mr + g) * 16 + j0 + tg];          qh_[ks][0] = t.x; ql_[ks][0] = t.y;
        t = qg[(mr + g + 8) * 16 + j0 + tg];      qh_[ks][1] = t.x; ql_[ks][1] = t.y;
        t = qg[(mr + g) * 16 + j0 + tg + 4];      qh_[ks][2] = t.x; ql_[ks][2] = t.y;
        t = qg[(mr + g + 8) * 16 + j0 + tg + 4];  qh_[ks][3] = t.x; ql_[ks][3] = t.y;
    }

    asm volatile("cp.async.wait_group 0;\n" ::: "memory");
    __syncthreads();

    // logits = q @ k^T  (q pre-scaled)
    float acc[8][4];
#pragma unroll
    for (int a = 0; a < 8; a++)
#pragma unroll
        for (int c = 0; c < 4; c++) acc[a][c] = 0.f;

#pragma unroll
    for (int ks = 0; ks < 2; ks++) {
        int j0 = ks * 8;
#pragma unroll
        for (int nfp = 0; nfp < 4; nfp++) {
            int nf0 = 2 * nfp, nf1 = nf0 + 1;
            int n0 = nf0 * 8 + g;
            uint2 c0 = k2s[n0][j0 + tg],     c1 = k2s[n0][j0 + tg + 4];
            uint2 d0 = k2s[n0 + 8][j0 + tg], d1 = k2s[n0 + 8][j0 + tg + 4];
            mma_bf16(acc[nf0], qh_[ks], c0.x, c1.x);
            mma_bf16(acc[nf1], qh_[ks], d0.x, d1.x);
            mma_bf16(acc[nf0], qh_[ks], c0.y, c1.y);
            mma_bf16(acc[nf1], qh_[ks], d0.y, d1.y);
            mma_bf16(acc[nf0], ql_[ks], c0.x, c1.x);
            mma_bf16(acc[nf1], ql_[ks], d0.x, d1.x);
        }
    }

    // combined bias+mask
    int r0 = mr + g, r1 = r0 + 8;
    const float* bmr = g_bm + (size_t)((b % NW) * 8 + h) * 4096;
#pragma unroll
    for (int nf = 0; nf < 8; nf++) {
        int n0 = nf * 8 + 2 * tg;
        float2 e0 = *(const float2*)(bmr + r0 * 64 + n0);
        float2 e1 = *(const float2*)(bmr + r1 * 64 + n0);
        acc[nf][0] += e0.x; acc[nf][1] += e0.y;
        acc[nf][2] += e1.x; acc[nf][3] += e1.y;
    }

    // softmax across the quad (rows r0, r1)
    float m0 = -1e30f, m1 = -1e30f;
#pragma unroll
    for (int nf = 0; nf < 8; nf++) {
        m0 = fmaxf(m0, fmaxf(acc[nf][0], acc[nf][1]));
        m1 = fmaxf(m1, fmaxf(acc[nf][2], acc[nf][3]));
    }
    m0 = fmaxf(m0, __shfl_xor_sync(0xffffffffu, m0, 1));
    m0 = fmaxf(m0, __shfl_xor_sync(0xffffffffu, m0, 2));
    m1 = fmaxf(m1, __shfl_xor_sync(0xffffffffu, m1, 1));
    m1 = fmaxf(m1, __shfl_xor_sync(0xffffffffu, m1, 2));

    float s0 = 0.f, s1 = 0.f;
#pragma unroll
    for (int nf = 0; nf < 8; nf++) {
        acc[nf][0] = __expf(acc[nf][0] - m0); s0 += acc[nf][0];
        acc[nf][1] = __expf(acc[nf][1] - m0); s0 += acc[nf][1];
        acc[nf][2] = __expf(acc[nf][2] - m1); s1 += acc[nf][2];
        acc[nf][3] = __expf(acc[nf][3] - m1); s1 += acc[nf][3];
    }
    s0 += __shfl_xor_sync(0xffffffffu, s0, 1);
    s0 += __shfl_xor_sync(0xffffffffu, s0, 2);
    s1 += __shfl_xor_sync(0xffffffffu, s1, 1);
    s1 += __shfl_xor_sync(0xffffffffu, s1, 2);
    float i0 = 1.f / s0, i1 = 1.f / s1;

    // out = P @ V  — P a-fragments straight from acc (lane-local)
    float oacc[4][4];
#pragma unroll
    for (int a = 0; a < 4; a++)
#pragma unroll
        for (int c = 0; c < 4; c++) oacc[a][c] = 0.f;

#pragma unroll
    for (int ks = 0; ks < 4; ks++) {
        uint32_t ah[4], al[4];
        split2(acc[2 * ks][0] * i0,     acc[2 * ks][1] * i0,     ah[0], al[0]);
        split2(acc[2 * ks][2] * i1,     acc[2 * ks][3] * i1,     ah[1], al[1]);
        split2(acc[2 * ks + 1][0] * i0, acc[2 * ks + 1][1] * i0, ah[2], al[2]);
        split2(acc[2 * ks + 1][2] * i1, acc[2 * ks + 1][3] * i1, ah[3], al[3]);
        int j0 = ks * 8;
#pragma unroll
        for (int nfp = 0; nfp < 2; nfp++) {
            int nf0 = 2 * nfp, nf1 = nf0 + 1;
            int n0 = nf0 * 8 + g;
            uint2 c0 = vt2[n0][j0 + tg],     c1 = vt2[n0][j0 + tg + 4];
            uint2 d0 = vt2[n0 + 8][j0 + tg], d1 = vt2[n0 + 8][j0 + tg + 4];
            mma_bf16(oacc[nf0], ah, c0.x, c1.x);
            mma_bf16(oacc[nf1], ah, d0.x, d1.x);
            mma_bf16(oacc[nf0], ah, c0.y, c1.y);
            mma_bf16(oacc[nf1], ah, d0.y, d1.y);
            mma_bf16(oacc[nf0], al, c0.x, c1.x);
            mma_bf16(oacc[nf1], al, d0.x, d1.x);
        }
    }

    // ctx -> proj operand planes
    int m0r = b * 64 + r0, m1r = b * 64 + r1;
#pragma unroll
    for (int nf = 0; nf < 4; nf++) {
        int dp = h * 16 + nf * 4 + tg;
        int kb = dp >> 4, q = dp & 15;
        uint32_t hi, lo;
        {
            size_t idx = ((size_t)((m0r >> 7) * 8 + kb)) * 2048 + plane_pair(m0r & 127, q);
            split2(oacc[nf][0], oacc[nf][1], hi, lo);
            g_othi[idx] = hi; g_otlo[idx] = lo;
        }
        {
            size_t idx = ((size_t)((m1r >> 7) * 8 + kb)) * 2048 + plane_pair(m1r & 127, q);
            split2(oacc[nf][2], oacc[nf][3], hi, lo);
            g_othi[idx] = hi; g_otlo[idx] = lo;
        }
    }
}

// ---------------------------------------------------------------------------
extern "C" void kernel_launch(void* const* d_in, const int* in_sizes, int n_in,
                              void* d_out, int out_size) {
    (void)in_sizes; (void)n_in; (void)out_size;
    const float* x       = (const float*)d_in[0];
    const float* mask    = (const float*)d_in[1];
    const float* qkv_w   = (const float*)d_in[2];
    const float* qkv_b   = (const float*)d_in[3];
    const float* proj_w  = (const float*)d_in[4];
    const float* proj_b  = (const float*)d_in[5];
    const float* pposw   = (const float*)d_in[6];
    const float* pposb   = (const float*)d_in[7];
    const float* ln1g    = (const float*)d_in[8];
    const float* ln1b    = (const float*)d_in[9];
    const float* fc1w    = (const float*)d_in[10];
    const float* fc1b    = (const float*)d_in[11];
    const float* ln2g    = (const float*)d_in[12];
    const float* ln2b    = (const float*)d_in[13];
    const float* fc2w    = (const float*)d_in[14];
    const float* fc2b    = (const float*)d_in[15];
    const float* ln3g    = (const float*)d_in[16];
    const float* ln3b    = (const float*)d_in[17];
    const float* fc3w    = (const float*)d_in[18];
    const float* fc3b    = (const float*)d_in[19];
    const float* biases  = (const float*)d_in[20];
    const int*   rel_idx = (const int*)d_in[21];
    float* out = (float*)d_out;

    static bool attr_set = false;
    if (!attr_set) {
        cudaFuncSetAttribute(gemm_kernel<0>, cudaFuncAttributeMaxDynamicSharedMemorySize, 98304);
        cudaFuncSetAttribute(gemm_kernel<1>, cudaFuncAttributeMaxDynamicSharedMemorySize, 98304);
        attr_set = true;
    }

    dpb_kernel<<<1, 256>>>(biases, pposw, pposb, ln1g, ln1b, fc1w, fc1b,
                           ln2g, ln2b, fc2w, fc2b, ln3g, ln3b, fc3w, fc3b);
    presplit_kernel<<<100864, 256>>>(x, qkv_w, proj_w);
    bmtab_kernel<<<dim3(NW, HEADS), 256>>>(mask, rel_idx);
    gemm_kernel<0><<<dim3(6, 1568), 256, 98304>>>(qkv_b, nullptr);
    attn_kernel<<<dim3(B_WIN, HEADS), 128>>>();
    gemm_kernel<1><<<dim3(2, 1568), 256, 98304>>>(proj_b, out);
}

// round 10
// speedup vs baseline: 1.8936x; 1.0230x over previous
#include <cuda_runtime.h>
#include <cuda_bf16.h>
#include <cstdint>
#include <math.h>

#define B_WIN   3136
#define NTOK    64
#define DIM     256
#define HEADS   8
#define NW      49
#define LBIAS   225
#define ATT_SCALE 0.17677669529663687f  // 1/sqrt(32)
#define LOG2E   1.4426950408889634f
#define ATT_SCALE_L2E (0.17677669529663687f * 1.4426950408889634f)

// ---------------------------------------------------------------------------
// Plane layout (see R7): per (tile128, kchunk32) chunk, 2048 uint32 pairs.
// ---------------------------------------------------------------------------
__device__ uint32_t g_xhi [25690112];
__device__ uint32_t g_xlo [25690112];
__device__ uint32_t g_othi[25690112];
__device__ uint32_t g_otlo[25690112];
__device__ uint32_t g_wqh [98304];
__device__ uint32_t g_wql [98304];
__device__ uint32_t g_wph [32768];
__device__ uint32_t g_wpl [32768];
__device__ uint2    g_q2  [25690112];  // [B_*H][64][16] packed hi/lo (log2e-scaled)
__device__ uint2    g_k2  [25690112];
__device__ float    g_v   [51380224];  // [B_*H][64][32] fp32
__device__ float    g_ptab[LBIAS * HEADS];
__device__ float    g_bm  [1605632];   // (bias+mask)*log2e  [49][8][64][64]

// ---------------------------------------------------------------------------
__device__ __forceinline__ void split2(float x, float y, uint32_t& hi, uint32_t& lo) {
    __nv_bfloat162 h = __floats2bfloat162_rn(x, y);
    float hx = __low2float(h), hy = __high2float(h);
    __nv_bfloat162 l = __floats2bfloat162_rn(x - hx, y - hy);
    hi = *reinterpret_cast<uint32_t*>(&h);
    lo = *reinterpret_cast<uint32_t*>(&l);
}

__device__ __forceinline__ uint32_t plane_pair(int r, int q) {
    int j = r >> 1;
    int u = (((r & 1) << 2) | (q >> 2)) ^ (j & 7);
    return (uint32_t)(j * 32 + u * 4 + (q & 3));
}

__device__ __forceinline__ void mma_bf16(float* c, const uint32_t* a, uint32_t b0, uint32_t b1) {
    asm volatile(
        "mma.sync.aligned.m16n8k16.row.col.f32.bf16.bf16.f32 "
        "{%0,%1,%2,%3}, {%4,%5,%6,%7}, {%8,%9}, {%0,%1,%2,%3};\n"
        : "+f"(c[0]), "+f"(c[1]), "+f"(c[2]), "+f"(c[3])
        : "r"(a[0]), "r"(a[1]), "r"(a[2]), "r"(a[3]), "r"(b0), "r"(b1));
}

__device__ __forceinline__ void ldsm4(uint32_t* r, uint32_t a) {
    asm volatile("ldmatrix.sync.aligned.m8n8.x4.shared.b16 {%0,%1,%2,%3}, [%4];"
                 : "=r"(r[0]), "=r"(r[1]), "=r"(r[2]), "=r"(r[3]) : "r"(a));
}

__device__ __forceinline__ void ldgsts16(uint32_t saddr, const void* gp) {
    asm volatile("cp.async.cg.shared.global [%0], [%1], 16;\n" :: "r"(saddr), "l"(gp));
}

__device__ __forceinline__ float ex2(float x) {
    float y;
    asm("ex2.approx.f32 %0, %1;" : "=f"(y) : "f"(x));
    return y;
}

// ---------------------------------------------------------------------------
// Kernel 1: DynamicPosBias MLP -> g_ptab[225][8]
// ---------------------------------------------------------------------------
__device__ __forceinline__ void lnrelu16(const float* p, float* t,
                                         const float* gm, const float* bt) {
    float m = 0.f;
#pragma unroll
    for (int j = 0; j < 16; j++) m += p[j];
    m *= (1.f / 16.f);
    float v = 0.f;
#pragma unroll
    for (int j = 0; j < 16; j++) { float d = p[j] - m; v += d * d; }
    v *= (1.f / 16.f);
    float is = rsqrtf(v + 1e-5f);
#pragma unroll
    for (int j = 0; j < 16; j++) {
        float u = (p[j] - m) * is * gm[j] + bt[j];
        t[j] = u > 0.f ? u : 0.f;
    }
}

__global__ void dpb_kernel(const float* __restrict__ biases,
                           const float* __restrict__ pw, const float* __restrict__ pb,
                           const float* __restrict__ g1, const float* __restrict__ b1,
                           const float* __restrict__ w1, const float* __restrict__ c1,
                           const float* __restrict__ g2, const float* __restrict__ b2,
                           const float* __restrict__ w2, const float* __restrict__ c2,
                           const float* __restrict__ g3, const float* __restrict__ b3,
                           const float* __restrict__ w3, const float* __restrict__ c3) {
    int r = threadIdx.x;
    if (r >= LBIAS) return;
    float p[16], t[16];
    float x0 = biases[2 * r], x1 = biases[2 * r + 1];
#pragma unroll
    for (int j = 0; j < 16; j++) p[j] = x0 * pw[2 * j] + x1 * pw[2 * j + 1] + pb[j];
    lnrelu16(p, t, g1, b1);
#pragma unroll
    for (int o = 0; o < 16; o++) {
        float s = c1[o];
#pragma unroll
        for (int j = 0; j < 16; j++) s += t[j] * w1[o * 16 + j];
        p[o] = s;
    }
    lnrelu16(p, t, g2, b2);
#pragma unroll
    for (int o = 0; o < 16; o++) {
        float s = c2[o];
#pragma unroll
        for (int j = 0; j < 16; j++) s += t[j] * w2[o * 16 + j];
        p[o] = s;
    }
    lnrelu16(p, t, g3, b3);
#pragma unroll
    for (int o = 0; o < 8; o++) {
        float s = c3[o];
#pragma unroll
        for (int j = 0; j < 16; j++) s += t[j] * w3[o * 16 + j];
        g_ptab[r * 8 + o] = s;
    }
}

// ---------------------------------------------------------------------------
// Kernel 1b: pre-split x / qkv_w / proj_w into plane chunks
// ---------------------------------------------------------------------------
__global__ void presplit_kernel(const float* __restrict__ x,
                                const float* __restrict__ qw,
                                const float* __restrict__ pw) {
    long i = (long)blockIdx.x * 256 + threadIdx.x;
    const float2* src; uint32_t *dh, *dl; long j;
    if (i < 25690112L) { j = i; src = (const float2*)x; dh = g_xhi; dl = g_xlo; }
    else if (i < 25690112L + 98304) { j = i - 25690112L; src = (const float2*)qw; dh = g_wqh; dl = g_wql; }
    else if (i < 25690112L + 98304 + 32768) { j = i - 25690112L - 98304; src = (const float2*)pw; dh = g_wph; dl = g_wpl; }
    else return;
    int m = (int)(j >> 7);
    int pc = (int)(j & 127);
    int tile = m >> 7, r = m & 127;
    int kb = pc >> 4, q = pc & 15;
    long idx = ((long)(tile * 8 + kb)) * 2048 + plane_pair(r, q);
    float2 f = src[j];
    uint32_t hi, lo;
    split2(f.x, f.y, hi, lo);
    dh[idx] = hi;
    dl[idx] = lo;
}

// ---------------------------------------------------------------------------
// Kernel 1c: combined (bias+mask)*log2e table
// ---------------------------------------------------------------------------
__global__ void bmtab_kernel(const float* __restrict__ mask,
                             const int* __restrict__ rel_idx) {
    int wb = blockIdx.x, h = blockIdx.y;
    float* dst = g_bm + (size_t)(wb * 8 + h) * 4096;
    const float* msk = mask + (size_t)wb * 4096;
    for (int i = threadIdx.x; i < 4096; i += blockDim.x)
        dst[i] = (g_ptab[rel_idx[i] * 8 + h] + msk[i]) * LOG2E;
}

// ---------------------------------------------------------------------------
// Kernel 2/4: HMMA GEMM (R8 mainloop — the 75%-tensor configuration).
// ---------------------------------------------------------------------------
template <int MODE>
__global__ __launch_bounds__(256, 2) void gemm_kernel(const float* __restrict__ bias,
                                                      float* __restrict__ Out) {
    extern __shared__ char smem[];
    uint32_t sb = (uint32_t)__cvta_generic_to_shared(smem);

    int bm = blockIdx.y, bn = blockIdx.x;
    int tid = threadIdx.x;
    int warp = tid >> 5, lane = tid & 31;
    int wm = warp >> 1, wn = warp & 1;
    int g = lane >> 2, tg = lane & 3;

    const uint32_t* Ah = MODE ? g_othi : g_xhi;
    const uint32_t* Al = MODE ? g_otlo : g_xlo;
    const uint32_t* Bh = MODE ? g_wph : g_wqh;
    const uint32_t* Bl = MODE ? g_wpl : g_wql;

    float acc[2][8][4];
#pragma unroll
    for (int a = 0; a < 2; a++)
#pragma unroll
        for (int b = 0; b < 8; b++)
#pragma unroll
            for (int c = 0; c < 4; c++) acc[a][b][c] = 0.f;

    auto mkbase = [&](int r, int lb) {
        int j = r >> 1, a = (r & 1) << 2;
        return (uint32_t)(j * 128 + (((a ^ lb) ^ (j & 7)) << 4));
    };
    int rA = lane & 15, lbA = lane >> 4;
    uint32_t baseA0 = mkbase(wm * 32 + rA, lbA);
    uint32_t baseA1 = mkbase(wm * 32 + 16 + rA, lbA);
    int rB = (lane & 7) | ((lane >> 1) & 8);
    int lbB = (lane >> 3) & 1;
    uint32_t baseB[4];
#pragma unroll
    for (int i = 0; i < 4; i++) baseB[i] = mkbase(wn * 64 + i * 16 + rB, lbB);

    auto issue = [&](int kb, int s) {
        uint32_t S = sb + (uint32_t)s * 32768;
        const uint32_t* srcs[4] = {
            Ah + (size_t)(bm * 8 + kb) * 2048, Al + (size_t)(bm * 8 + kb) * 2048,
            Bh + (size_t)(bn * 8 + kb) * 2048, Bl + (size_t)(bn * 8 + kb) * 2048 };
#pragma unroll
        for (int p = 0; p < 4; p++) {
#pragma unroll
            for (int e = 0; e < 2; e++) {
                int u = tid + e * 256;
                ldgsts16(S + (uint32_t)p * 8192 + u * 16, srcs[p] + u * 4);
            }
        }
        asm volatile("cp.async.commit_group;\n" ::: "memory");
    };

    issue(0, 0);
    issue(1, 1);

    for (int kb = 0; kb < 8; kb++) {
        int s = kb % 3;
        if (kb < 7) asm volatile("cp.async.wait_group 1;\n" ::: "memory");
        else        asm volatile("cp.async.wait_group 0;\n" ::: "memory");
        __syncthreads();

        uint32_t S = sb + (uint32_t)s * 32768;
#pragma unroll
        for (int ks = 0; ks < 2; ks++) {
            uint32_t uo = ks * 32;
            uint32_t ah0[4], ah1[4], al0[4], al1[4];
            ldsm4(ah0, S + (baseA0 ^ uo));
            ldsm4(ah1, S + (baseA1 ^ uo));
            ldsm4(al0, S + 8192 + (baseA0 ^ uo));
            ldsm4(al1, S + 8192 + (baseA1 ^ uo));
#pragma unroll
            for (int nfp = 0; nfp < 4; nfp++) {
                int nf0 = 2 * nfp, nf1 = nf0 + 1;
                uint32_t bh[4], bl[4];
                ldsm4(bh, S + 16384 + (baseB[nfp] ^ uo));
                ldsm4(bl, S + 24576 + (baseB[nfp] ^ uo));
                mma_bf16(acc[0][nf0], ah0, bh[0], bh[1]);
                mma_bf16(acc[1][nf0], ah1, bh[0], bh[1]);
                mma_bf16(acc[0][nf1], ah0, bh[2], bh[3]);
                mma_bf16(acc[1][nf1], ah1, bh[2], bh[3]);
                mma_bf16(acc[0][nf0], ah0, bl[0], bl[1]);
                mma_bf16(acc[1][nf0], ah1, bl[0], bl[1]);
                mma_bf16(acc[0][nf1], ah0, bl[2], bl[3]);
                mma_bf16(acc[1][nf1], ah1, bl[2], bl[3]);
                mma_bf16(acc[0][nf0], al0, bh[0], bh[1]);
                mma_bf16(acc[1][nf0], al1, bh[0], bh[1]);
                mma_bf16(acc[0][nf1], al0, bh[2], bh[3]);
                mma_bf16(acc[1][nf1], al1, bh[2], bh[3]);
            }
        }
        if (kb < 6) issue(kb + 2, (kb + 2) % 3);
    }

    int obase = bn * 128 + wn * 64;
#pragma unroll
    for (int nf = 0; nf < 8; nf++) {
        int o = obase + nf * 8 + 2 * tg;
        float bb0 = bias[o], bb1 = bias[o + 1];
#pragma unroll
        for (int mf = 0; mf < 2; mf++) {
#pragma unroll
            for (int r2 = 0; r2 < 2; r2++) {
                int m = bm * 128 + wm * 32 + mf * 16 + g + r2 * 8;
                float v0 = acc[mf][nf][r2 * 2] + bb0;
                float v1 = acc[mf][nf][r2 * 2 + 1] + bb1;
                if (MODE == 1) {
                    *(float2*)(Out + (size_t)m * 256 + o) = make_float2(v0, v1);
                } else {
                    int s = o >> 8, hh = (o >> 5) & 7, d = o & 31;
                    int bw = m >> 6, n = m & 63;
                    size_t di = ((size_t)(bw * 8 + hh) * 64 + n) * 16 + (d >> 1);
                    if (s == 0)      { uint2 u; split2(v0 * ATT_SCALE_L2E, v1 * ATT_SCALE_L2E, u.x, u.y); g_q2[di] = u; }
                    else if (s == 1) { uint2 u; split2(v0, v1, u.x, u.y); g_k2[di] = u; }
                    else             { *(float2*)(g_v + (di << 1)) = make_float2(v0, v1); }
                }
            }
        }
    }
}

// ---------------------------------------------------------------------------
// Kernel 3: attention per (window b, head h). 4 warps, 16 query rows each.
// k AND bias+mask prefetched via cp.async; softmax in log2 domain (ex2).
// ---------------------------------------------------------------------------
__global__ __launch_bounds__(128, 6) void attn_kernel() {
    __shared__ uint2 k2s[64][20];
    __shared__ uint2 vt2[32][36];   // V^T: [d][token-pair]
    __shared__ float bms[64][68];   // (bias+mask)*log2e, row stride 272B

    int b = blockIdx.x, h = blockIdx.y;
    int tid = threadIdx.x;
    int warp = tid >> 5, lane = tid & 31;
    int g = lane >> 2, tg = lane & 3;
    int mr = warp * 16;

    const uint2* qg = g_q2 + (size_t)(b * 8 + h) * 1024;
    const uint2* kg = g_k2 + (size_t)(b * 8 + h) * 1024;
    const float* vg = g_v  + (size_t)(b * 8 + h) * 2048;
    const float* bmr = g_bm + (size_t)((b % NW) * 8 + h) * 4096;

    // k tile via cp.async (group 0)
#pragma unroll
    for (int e = 0; e < 4; e++) {
        int it = tid + e * 128;
        int t = it >> 3, j = (it & 7) * 2;
        ldgsts16((uint32_t)__cvta_generic_to_shared(&k2s[t][j]), kg + t * 16 + j);
    }
    asm volatile("cp.async.commit_group;\n" ::: "memory");

    // bias+mask tile via cp.async (group 1); each warp loads its own 16 rows
    uint32_t bmsb = (uint32_t)__cvta_generic_to_shared(&bms[0][0]);
#pragma unroll
    for (int e = 0; e < 8; e++) {
        int i = lane + 32 * e;               // 0..255
        int rr = warp * 16 + (i >> 4);
        int cu = (i & 15) * 4;               // float col of 16B unit
        ldgsts16(bmsb + (uint32_t)(rr * 68 + cu) * 4, bmr + rr * 64 + cu);
    }
    asm volatile("cp.async.commit_group;\n" ::: "memory");

    // v: fp32 -> split -> V^T smem
    for (int it = tid; it < 1024; it += 128) {
        int d = it & 31, j = it >> 5;
        uint2 u;
        split2(vg[(2 * j) * 32 + d], vg[(2 * j + 1) * 32 + d], u.x, u.y);
        vt2[d][j] = u;
    }

    // q fragments straight from gmem
    uint32_t qh_[2][4], ql_[2][4];
#pragma unroll
    for (int ks = 0; ks < 2; ks++) {
        int j0 = ks * 8;
        uint2 t;
        t = qg[(mr + g) * 16 + j0 + tg];          qh_[ks][0] = t.x; ql_[ks][0] = t.y;
        t = qg[(mr + g + 8) * 16 + j0 + tg];      qh_[ks][1] = t.x; ql_[ks][1] = t.y;
        t = qg[(mr + g) * 16 + j0 + tg + 4];      qh_[ks][2] = t.x; ql_[ks][2] = t.y;
        t = qg[(mr + g + 8) * 16 + j0 + tg + 4];  qh_[ks][3] = t.x; ql_[ks][3] = t.y;
    }

    asm volatile("cp.async.wait_group 1;\n" ::: "memory");  // k done (bm may fly)
    __syncthreads();

    // logits(log2) = q @ k^T  (q pre-scaled by scale*log2e)
    float acc[8][4];
#pragma unroll
    for (int a = 0; a < 8; a++)
#pragma unroll
        for (int c = 0; c < 4; c++) acc[a][c] = 0.f;

#pragma unroll
    for (int ks = 0; ks < 2; ks++) {
        int j0 = ks * 8;
#pragma unroll
        for (int nfp = 0; nfp < 4; nfp++) {
            int nf0 = 2 * nfp, nf1 = nf0 + 1;
            int n0 = nf0 * 8 + g;
            uint2 c0 = k2s[n0][j0 + tg],     c1 = k2s[n0][j0 + tg + 4];
            uint2 d0 = k2s[n0 + 8][j0 + tg], d1 = k2s[n0 + 8][j0 + tg + 4];
            mma_bf16(acc[nf0], qh_[ks], c0.x, c1.x);
            mma_bf16(acc[nf1], qh_[ks], d0.x, d1.x);
            mma_bf16(acc[nf0], qh_[ks], c0.y, c1.y);
            mma_bf16(acc[nf1], qh_[ks], d0.y, d1.y);
            mma_bf16(acc[nf0], ql_[ks], c0.x, c1.x);
            mma_bf16(acc[nf1], ql_[ks], d0.x, d1.x);
        }
    }

    // bias+mask from prefetched smem (own warp's rows: wait + syncwarp suffice)
    asm volatile("cp.async.wait_group 0;\n" ::: "memory");
    __syncwarp();
    int r0 = mr + g, r1 = r0 + 8;
#pragma unroll
    for (int nf = 0; nf < 8; nf++) {
        int n0 = nf * 8 + 2 * tg;
        float2 e0 = *(const float2*)(&bms[r0][n0]);
        float2 e1 = *(const float2*)(&bms[r1][n0]);
        acc[nf][0] += e0.x; acc[nf][1] += e0.y;
        acc[nf][2] += e1.x; acc[nf][3] += e1.y;
    }

    // softmax (log2 domain) across the quad (rows r0, r1)
    float m0 = -1e30f, m1 = -1e30f;
#pragma unroll
    for (int nf = 0; nf < 8; nf++) {
        m0 = fmaxf(m0, fmaxf(acc[nf][0], acc[nf][1]));
        m1 = fmaxf(m1, fmaxf(acc[nf][2], acc[nf][3]));
    }
    m0 = fmaxf(m0, __shfl_xor_sync(0xffffffffu, m0, 1));
    m0 = fmaxf(m0, __shfl_xor_sync(0xffffffffu, m0, 2));
    m1 = fmaxf(m1, __shfl_xor_sync(0xffffffffu, m1, 1));
    m1 = fmaxf(m1, __shfl_xor_sync(0xffffffffu, m1, 2));

    float s0 = 0.f, s1 = 0.f;
#pragma unroll
    for (int nf = 0; nf < 8; nf++) {
        acc[nf][0] = ex2(acc[nf][0] - m0); s0 += acc[nf][0];
        acc[nf][1] = ex2(acc[nf][1] - m0); s0 += acc[nf][1];
        acc[nf][2] = ex2(acc[nf][2] - m1); s1 += acc[nf][2];
        acc[nf][3] = ex2(acc[nf][3] - m1); s1 += acc[nf][3];
    }
    s0 += __shfl_xor_sync(0xffffffffu, s0, 1);
    s0 += __shfl_xor_sync(0xffffffffu, s0, 2);
    s1 += __shfl_xor_sync(0xffffffffu, s1, 1);
    s1 += __shfl_xor_sync(0xffffffffu, s1, 2);
    float i0 = 1.f / s0, i1 = 1.f / s1;

    // out = P @ V  — P a-fragments straight from acc (lane-local)
    float oacc[4][4];
#pragma unroll
    for (int a = 0; a < 4; a++)
#pragma unroll
        for (int c = 0; c < 4; c++) oacc[a][c] = 0.f;

#pragma unroll
    for (int ks = 0; ks < 4; ks++) {
        uint32_t ah[4], al[4];
        split2(acc[2 * ks][0] * i0,     acc[2 * ks][1] * i0,     ah[0], al[0]);
        split2(acc[2 * ks][2] * i1,     acc[2 * ks][3] * i1,     ah[1], al[1]);
        split2(acc[2 * ks + 1][0] * i0, acc[2 * ks + 1][1] * i0, ah[2], al[2]);
        split2(acc[2 * ks + 1][2] * i1, acc[2 * ks + 1][3] * i1, ah[3], al[3]);
        int j0 = ks * 8;
#pragma unroll
        for (int nfp = 0; nfp < 2; nfp++) {
            int nf0 = 2 * nfp, nf1 = nf0 + 1;
            int n0 = nf0 * 8 + g;
            uint2 c0 = vt2[n0][j0 + tg],     c1 = vt2[n0][j0 + tg + 4];
            uint2 d0 = vt2[n0 + 8][j0 + tg], d1 = vt2[n0 + 8][j0 + tg + 4];
            mma_bf16(oacc[nf0], ah, c0.x, c1.x);
            mma_bf16(oacc[nf1], ah, d0.x, d1.x);
            mma_bf16(oacc[nf0], ah, c0.y, c1.y);
            mma_bf16(oacc[nf1], ah, d0.y, d1.y);
            mma_bf16(oacc[nf0], al, c0.x, c1.x);
            mma_bf16(oacc[nf1], al, d0.x, d1.x);
        }
    }

    // ctx -> proj operand planes
    int m0r = b * 64 + r0, m1r = b * 64 + r1;
#pragma unroll
    for (int nf = 0; nf < 4; nf++) {
        int dp = h * 16 + nf * 4 + tg;
        int kb = dp >> 4, q = dp & 15;
        uint32_t hi, lo;
        {
            size_t idx = ((size_t)((m0r >> 7) * 8 + kb)) * 2048 + plane_pair(m0r & 127, q);
            split2(oacc[nf][0], oacc[nf][1], hi, lo);
            g_othi[idx] = hi; g_otlo[idx] = lo;
        }
        {
            size_t idx = ((size_t)((m1r >> 7) * 8 + kb)) * 2048 + plane_pair(m1r & 127, q);
            split2(oacc[nf][2], oacc[nf][3], hi, lo);
            g_othi[idx] = hi; g_otlo[idx] = lo;
        }
    }
}

// ---------------------------------------------------------------------------
extern "C" void kernel_launch(void* const* d_in, const int* in_sizes, int n_in,
                              void* d_out, int out_size) {
    (void)in_sizes; (void)n_in; (void)out_size;
    const float* x       = (const float*)d_in[0];
    const float* mask    = (const float*)d_in[1];
    const float* qkv_w   = (const float*)d_in[2];
    const float* qkv_b   = (const float*)d_in[3];
    const float* proj_w  = (const float*)d_in[4];
    const float* proj_b  = (const float*)d_in[5];
    const float* pposw   = (const float*)d_in[6];
    const float* pposb   = (const float*)d_in[7];
    const float* ln1g    = (const float*)d_in[8];
    const float* ln1b    = (const float*)d_in[9];
    const float* fc1w    = (const float*)d_in[10];
    const float* fc1b    = (const float*)d_in[11];
    const float* ln2g    = (const float*)d_in[12];
    const float* ln2b    = (const float*)d_in[13];
    const float* fc2w    = (const float*)d_in[14];
    const float* fc2b    = (const float*)d_in[15];
    const float* ln3g    = (const float*)d_in[16];
    const float* ln3b    = (const float*)d_in[17];
    const float* fc3w    = (const float*)d_in[18];
    const float* fc3b    = (const float*)d_in[19];
    const float* biases  = (const float*)d_in[20];
    const int*   rel_idx = (const int*)d_in[21];
    float* out = (float*)d_out;

    static bool attr_set = false;
    if (!attr_set) {
        cudaFuncSetAttribute(gemm_kernel<0>, cudaFuncAttributeMaxDynamicSharedMemorySize, 98304);
        cudaFuncSetAttribute(gemm_kernel<1>, cudaFuncAttributeMaxDynamicSharedMemorySize, 98304);
        attr_set = true;
    }

    dpb_kernel<<<1, 256>>>(biases, pposw, pposb, ln1g, ln1b, fc1w, fc1b,
                           ln2g, ln2b, fc2w, fc2b, ln3g, ln3b, fc3w, fc3b);
    presplit_kernel<<<100864, 256>>>(x, qkv_w, proj_w);
    bmtab_kernel<<<dim3(NW, HEADS), 256>>>(mask, rel_idx);
    gemm_kernel<0><<<dim3(6, 1568), 256, 98304>>>(qkv_b, nullptr);
    attn_kernel<<<dim3(B_WIN, HEADS), 128>>>();
    gemm_kernel<1><<<dim3(2, 1568), 256, 98304>>>(proj_b, out);
}

// round 11
// speedup vs baseline: 2.0685x; 1.0924x over previous
#include <cuda_runtime.h>
#include <cuda_bf16.h>
#include <cstdint>
#include <math.h>

#define B_WIN   3136
#define NTOK    64
#define DIM     256
#define HEADS   8
#define NW      49
#define LBIAS   225
#define ATT_SCALE 0.17677669529663687f  // 1/sqrt(32)
#define LOG2E   1.4426950408889634f
#define ATT_SCALE_L2E (0.17677669529663687f * 1.4426950408889634f)

// ---------------------------------------------------------------------------
// Plane layout (see R7): per (tile128, kchunk32) chunk, 2048 uint32 pairs.
// ---------------------------------------------------------------------------
__device__ uint32_t g_xhi [25690112];
__device__ uint32_t g_xlo [25690112];
__device__ uint32_t g_othi[25690112];
__device__ uint32_t g_otlo[25690112];
__device__ uint32_t g_wqh [98304];
__device__ uint32_t g_wql [98304];
__device__ uint32_t g_wph [32768];
__device__ uint32_t g_wpl [32768];
__device__ uint2    g_q2  [25690112];  // [B_*H][64][16] packed hi/lo (log2e-scaled)
__device__ uint2    g_k2  [25690112];
__device__ uint32_t g_vh  [25690112];  // v hi plane: [B_*H][64][16] bf16x2
__device__ uint32_t g_vl  [25690112];  // v lo plane
__device__ float    g_ptab[LBIAS * HEADS];
__device__ float    g_bm  [1605632];   // (bias+mask)*log2e  [49][8][64][64]

// ---------------------------------------------------------------------------
__device__ __forceinline__ void split2(float x, float y, uint32_t& hi, uint32_t& lo) {
    __nv_bfloat162 h = __floats2bfloat162_rn(x, y);
    float hx = __low2float(h), hy = __high2float(h);
    __nv_bfloat162 l = __floats2bfloat162_rn(x - hx, y - hy);
    hi = *reinterpret_cast<uint32_t*>(&h);
    lo = *reinterpret_cast<uint32_t*>(&l);
}

__device__ __forceinline__ uint32_t plane_pair(int r, int q) {
    int j = r >> 1;
    int u = (((r & 1) << 2) | (q >> 2)) ^ (j & 7);
    return (uint32_t)(j * 32 + u * 4 + (q & 3));
}

__device__ __forceinline__ void mma_bf16(float* c, const uint32_t* a, uint32_t b0, uint32_t b1) {
    asm volatile(
        "mma.sync.aligned.m16n8k16.row.col.f32.bf16.bf16.f32 "
        "{%0,%1,%2,%3}, {%4,%5,%6,%7}, {%8,%9}, {%0,%1,%2,%3};\n"
        : "+f"(c[0]), "+f"(c[1]), "+f"(c[2]), "+f"(c[3])
        : "r"(a[0]), "r"(a[1]), "r"(a[2]), "r"(a[3]), "r"(b0), "r"(b1));
}

__device__ __forceinline__ void ldsm4(uint32_t* r, uint32_t a) {
    asm volatile("ldmatrix.sync.aligned.m8n8.x4.shared.b16 {%0,%1,%2,%3}, [%4];"
                 : "=r"(r[0]), "=r"(r[1]), "=r"(r[2]), "=r"(r[3]) : "r"(a));
}

__device__ __forceinline__ void ldsm4t(uint32_t* r, uint32_t a) {
    asm volatile("ldmatrix.sync.aligned.m8n8.x4.trans.shared.b16 {%0,%1,%2,%3}, [%4];"
                 : "=r"(r[0]), "=r"(r[1]), "=r"(r[2]), "=r"(r[3]) : "r"(a));
}

__device__ __forceinline__ void ldgsts16(uint32_t saddr, const void* gp) {
    asm volatile("cp.async.cg.shared.global [%0], [%1], 16;\n" :: "r"(saddr), "l"(gp));
}

__device__ __forceinline__ float ex2(float x) {
    float y;
    asm("ex2.approx.f32 %0, %1;" : "=f"(y) : "f"(x));
    return y;
}

// ---------------------------------------------------------------------------
// Kernel 1: DynamicPosBias MLP -> g_ptab[225][8]
// ---------------------------------------------------------------------------
__device__ __forceinline__ void lnrelu16(const float* p, float* t,
                                         const float* gm, const float* bt) {
    float m = 0.f;
#pragma unroll
    for (int j = 0; j < 16; j++) m += p[j];
    m *= (1.f / 16.f);
    float v = 0.f;
#pragma unroll
    for (int j = 0; j < 16; j++) { float d = p[j] - m; v += d * d; }
    v *= (1.f / 16.f);
    float is = rsqrtf(v + 1e-5f);
#pragma unroll
    for (int j = 0; j < 16; j++) {
        float u = (p[j] - m) * is * gm[j] + bt[j];
        t[j] = u > 0.f ? u : 0.f;
    }
}

__global__ void dpb_kernel(const float* __restrict__ biases,
                           const float* __restrict__ pw, const float* __restrict__ pb,
                           const float* __restrict__ g1, const float* __restrict__ b1,
                           const float* __restrict__ w1, const float* __restrict__ c1,
                           const float* __restrict__ g2, const float* __restrict__ b2,
                           const float* __restrict__ w2, const float* __restrict__ c2,
                           const float* __restrict__ g3, const float* __restrict__ b3,
                           const float* __restrict__ w3, const float* __restrict__ c3) {
    int r = threadIdx.x;
    if (r >= LBIAS) return;
    float p[16], t[16];
    float x0 = biases[2 * r], x1 = biases[2 * r + 1];
#pragma unroll
    for (int j = 0; j < 16; j++) p[j] = x0 * pw[2 * j] + x1 * pw[2 * j + 1] + pb[j];
    lnrelu16(p, t, g1, b1);
#pragma unroll
    for (int o = 0; o < 16; o++) {
        float s = c1[o];
#pragma unroll
        for (int j = 0; j < 16; j++) s += t[j] * w1[o * 16 + j];
        p[o] = s;
    }
    lnrelu16(p, t, g2, b2);
#pragma unroll
    for (int o = 0; o < 16; o++) {
        float s = c2[o];
#pragma unroll
        for (int j = 0; j < 16; j++) s += t[j] * w2[o * 16 + j];
        p[o] = s;
    }
    lnrelu16(p, t, g3, b3);
#pragma unroll
    for (int o = 0; o < 8; o++) {
        float s = c3[o];
#pragma unroll
        for (int j = 0; j < 16; j++) s += t[j] * w3[o * 16 + j];
        g_ptab[r * 8 + o] = s;
    }
}

// ---------------------------------------------------------------------------
// Kernel 1b: pre-split x / qkv_w / proj_w into plane chunks (float4/thread)
// ---------------------------------------------------------------------------
__global__ void presplit_kernel(const float* __restrict__ x,
                                const float* __restrict__ qw,
                                const float* __restrict__ pw) {
    long i = (long)blockIdx.x * 256 + threadIdx.x;  // handles pairs 2i, 2i+1
    const float4* src; uint32_t *dh, *dl; long j2;
    if (i < 12845056L) { j2 = 2 * i; src = (const float4*)x; dh = g_xhi; dl = g_xlo; }
    else if (i < 12845056L + 49152) { j2 = 2 * (i - 12845056L); src = (const float4*)qw; dh = g_wqh; dl = g_wql; }
    else if (i < 12845056L + 49152 + 16384) { j2 = 2 * (i - 12845056L - 49152); src = (const float4*)pw; dh = g_wph; dl = g_wpl; }
    else return;
    float4 f = src[j2 >> 1];
    int m = (int)(j2 >> 7);
    int pc = (int)(j2 & 127);           // even
    int tile = m >> 7, r = m & 127;
    int kb = pc >> 4, q = pc & 15;      // q even -> idx, idx+1 consecutive
    long idx = ((long)(tile * 8 + kb)) * 2048 + plane_pair(r, q);
    uint32_t h0, l0, h1, l1;
    split2(f.x, f.y, h0, l0);
    split2(f.z, f.w, h1, l1);
    *(uint2*)(dh + idx) = make_uint2(h0, h1);
    *(uint2*)(dl + idx) = make_uint2(l0, l1);
}

// ---------------------------------------------------------------------------
// Kernel 1c: combined (bias+mask)*log2e table
// ---------------------------------------------------------------------------
__global__ void bmtab_kernel(const float* __restrict__ mask,
                             const int* __restrict__ rel_idx) {
    int wb = blockIdx.x, h = blockIdx.y;
    float* dst = g_bm + (size_t)(wb * 8 + h) * 4096;
    const float* msk = mask + (size_t)wb * 4096;
    for (int i = threadIdx.x; i < 4096; i += blockDim.x)
        dst[i] = (g_ptab[rel_idx[i] * 8 + h] + msk[i]) * LOG2E;
}

// ---------------------------------------------------------------------------
// Kernel 2/4: HMMA GEMM (R8/R10 mainloop — 75%-tensor configuration).
// ---------------------------------------------------------------------------
template <int MODE>
__global__ __launch_bounds__(256, 2) void gemm_kernel(const float* __restrict__ bias,
                                                      float* __restrict__ Out) {
    extern __shared__ char smem[];
    uint32_t sb = (uint32_t)__cvta_generic_to_shared(smem);

    int bm = blockIdx.y, bn = blockIdx.x;
    int tid = threadIdx.x;
    int warp = tid >> 5, lane = tid & 31;
    int wm = warp >> 1, wn = warp & 1;
    int g = lane >> 2, tg = lane & 3;

    const uint32_t* Ah = MODE ? g_othi : g_xhi;
    const uint32_t* Al = MODE ? g_otlo : g_xlo;
    const uint32_t* Bh = MODE ? g_wph : g_wqh;
    const uint32_t* Bl = MODE ? g_wpl : g_wql;

    float acc[2][8][4];
#pragma unroll
    for (int a = 0; a < 2; a++)
#pragma unroll
        for (int b = 0; b < 8; b++)
#pragma unroll
            for (int c = 0; c < 4; c++) acc[a][b][c] = 0.f;

    auto mkbase = [&](int r, int lb) {
        int j = r >> 1, a = (r & 1) << 2;
        return (uint32_t)(j * 128 + (((a ^ lb) ^ (j & 7)) << 4));
    };
    int rA = lane & 15, lbA = lane >> 4;
    uint32_t baseA0 = mkbase(wm * 32 + rA, lbA);
    uint32_t baseA1 = mkbase(wm * 32 + 16 + rA, lbA);
    int rB = (lane & 7) | ((lane >> 1) & 8);
    int lbB = (lane >> 3) & 1;
    uint32_t baseB[4];
#pragma unroll
    for (int i = 0; i < 4; i++) baseB[i] = mkbase(wn * 64 + i * 16 + rB, lbB);

    auto issue = [&](int kb, int s) {
        uint32_t S = sb + (uint32_t)s * 32768;
        const uint32_t* srcs[4] = {
            Ah + (size_t)(bm * 8 + kb) * 2048, Al + (size_t)(bm * 8 + kb) * 2048,
            Bh + (size_t)(bn * 8 + kb) * 2048, Bl + (size_t)(bn * 8 + kb) * 2048 };
#pragma unroll
        for (int p = 0; p < 4; p++) {
#pragma unroll
            for (int e = 0; e < 2; e++) {
                int u = tid + e * 256;
                ldgsts16(S + (uint32_t)p * 8192 + u * 16, srcs[p] + u * 4);
            }
        }
        asm volatile("cp.async.commit_group;\n" ::: "memory");
    };

    issue(0, 0);
    issue(1, 1);

    for (int kb = 0; kb < 8; kb++) {
        int s = kb % 3;
        if (kb < 7) asm volatile("cp.async.wait_group 1;\n" ::: "memory");
        else        asm volatile("cp.async.wait_group 0;\n" ::: "memory");
        __syncthreads();

        uint32_t S = sb + (uint32_t)s * 32768;
#pragma unroll
        for (int ks = 0; ks < 2; ks++) {
            uint32_t uo = ks * 32;
            uint32_t ah0[4], ah1[4], al0[4], al1[4];
            ldsm4(ah0, S + (baseA0 ^ uo));
            ldsm4(ah1, S + (baseA1 ^ uo));
            ldsm4(al0, S + 8192 + (baseA0 ^ uo));
            ldsm4(al1, S + 8192 + (baseA1 ^ uo));
#pragma unroll
            for (int nfp = 0; nfp < 4; nfp++) {
                int nf0 = 2 * nfp, nf1 = nf0 + 1;
                uint32_t bh[4], bl[4];
                ldsm4(bh, S + 16384 + (baseB[nfp] ^ uo));
                ldsm4(bl, S + 24576 + (baseB[nfp] ^ uo));
                mma_bf16(acc[0][nf0], ah0, bh[0], bh[1]);
                mma_bf16(acc[1][nf0], ah1, bh[0], bh[1]);
                mma_bf16(acc[0][nf1], ah0, bh[2], bh[3]);
                mma_bf16(acc[1][nf1], ah1, bh[2], bh[3]);
                mma_bf16(acc[0][nf0], ah0, bl[0], bl[1]);
                mma_bf16(acc[1][nf0], ah1, bl[0], bl[1]);
                mma_bf16(acc[0][nf1], ah0, bl[2], bl[3]);
                mma_bf16(acc[1][nf1], ah1, bl[2], bl[3]);
                mma_bf16(acc[0][nf0], al0, bh[0], bh[1]);
                mma_bf16(acc[1][nf0], al1, bh[0], bh[1]);
                mma_bf16(acc[0][nf1], al0, bh[2], bh[3]);
                mma_bf16(acc[1][nf1], al1, bh[2], bh[3]);
            }
        }
        if (kb < 6) issue(kb + 2, (kb + 2) % 3);
    }

    int obase = bn * 128 + wn * 64;
#pragma unroll
    for (int nf = 0; nf < 8; nf++) {
        int o = obase + nf * 8 + 2 * tg;
        float bb0 = bias[o], bb1 = bias[o + 1];
#pragma unroll
        for (int mf = 0; mf < 2; mf++) {
#pragma unroll
            for (int r2 = 0; r2 < 2; r2++) {
                int m = bm * 128 + wm * 32 + mf * 16 + g + r2 * 8;
                float v0 = acc[mf][nf][r2 * 2] + bb0;
                float v1 = acc[mf][nf][r2 * 2 + 1] + bb1;
                if (MODE == 1) {
                    *(float2*)(Out + (size_t)m * 256 + o) = make_float2(v0, v1);
                } else {
                    int s = o >> 8, hh = (o >> 5) & 7, d = o & 31;
                    int bw = m >> 6, n = m & 63;
                    size_t di = ((size_t)(bw * 8 + hh) * 64 + n) * 16 + (d >> 1);
                    uint32_t hi, lo;
                    if (s == 0)      { uint2 u; split2(v0 * ATT_SCALE_L2E, v1 * ATT_SCALE_L2E, u.x, u.y); g_q2[di] = u; }
                    else if (s == 1) { uint2 u; split2(v0, v1, u.x, u.y); g_k2[di] = u; }
                    else             { split2(v0, v1, hi, lo); g_vh[di] = hi; g_vl[di] = lo; }
                }
            }
        }
    }
}

// ---------------------------------------------------------------------------
// Kernel 3: attention per (window b, head h). 4 warps, 16 query rows each.
// k / v-planes / bias+mask all cp.async prefetched; V b-frags via
// ldmatrix.trans on row-major v planes; softmax in log2 domain.
// smem rows of v planes are 80B -> conflict-free LDSM phases.
// ---------------------------------------------------------------------------
__global__ __launch_bounds__(128, 6) void attn_kernel() {
    __shared__ uint2    k2s[64][20];
    __shared__ uint32_t vhs[64][20];  // v hi plane rows (64B data + 16B pad)
    __shared__ uint32_t vls[64][20];
    __shared__ float    bms[64][68];

    int b = blockIdx.x, h = blockIdx.y;
    int tid = threadIdx.x;
    int warp = tid >> 5, lane = tid & 31;
    int g = lane >> 2, tg = lane & 3;
    int mr = warp * 16;

    const uint2*    qg = g_q2 + (size_t)(b * 8 + h) * 1024;
    const uint2*    kg = g_k2 + (size_t)(b * 8 + h) * 1024;
    const uint32_t* vhg = g_vh + (size_t)(b * 8 + h) * 1024;
    const uint32_t* vlg = g_vl + (size_t)(b * 8 + h) * 1024;
    const float*    bmr = g_bm + (size_t)((b % NW) * 8 + h) * 4096;

    // group 0: k tile
#pragma unroll
    for (int e = 0; e < 4; e++) {
        int it = tid + e * 128;
        int t = it >> 3, j = (it & 7) * 2;
        ldgsts16((uint32_t)__cvta_generic_to_shared(&k2s[t][j]), kg + t * 16 + j);
    }
    asm volatile("cp.async.commit_group;\n" ::: "memory");

    // group 1: v planes (256 16B units each)
    uint32_t vhb = (uint32_t)__cvta_generic_to_shared(&vhs[0][0]);
    uint32_t vlb = (uint32_t)__cvta_generic_to_shared(&vls[0][0]);
#pragma unroll
    for (int e = 0; e < 2; e++) {
        int u = tid + e * 128;            // 0..255
        int t = u >> 2, part = u & 3;
        ldgsts16(vhb + (uint32_t)(t * 80 + part * 16), vhg + t * 16 + part * 4);
        ldgsts16(vlb + (uint32_t)(t * 80 + part * 16), vlg + t * 16 + part * 4);
    }
    asm volatile("cp.async.commit_group;\n" ::: "memory");

    // group 2: bias+mask tile (each warp its own 16 rows)
    uint32_t bmsb = (uint32_t)__cvta_generic_to_shared(&bms[0][0]);
#pragma unroll
    for (int e = 0; e < 8; e++) {
        int i = lane + 32 * e;
        int rr = warp * 16 + (i >> 4);
        int cu = (i & 15) * 4;
        ldgsts16(bmsb + (uint32_t)(rr * 68 + cu) * 4, bmr + rr * 64 + cu);
    }
    asm volatile("cp.async.commit_group;\n" ::: "memory");

    // q fragments straight from gmem
    uint32_t qh_[2][4], ql_[2][4];
#pragma unroll
    for (int ks = 0; ks < 2; ks++) {
        int j0 = ks * 8;
        uint2 t;
        t = qg[(mr + g) * 16 + j0 + tg];          qh_[ks][0] = t.x; ql_[ks][0] = t.y;
        t = qg[(mr + g + 8) * 16 + j0 + tg];      qh_[ks][1] = t.x; ql_[ks][1] = t.y;
        t = qg[(mr + g) * 16 + j0 + tg + 4];      qh_[ks][2] = t.x; ql_[ks][2] = t.y;
        t = qg[(mr + g + 8) * 16 + j0 + tg + 4];  qh_[ks][3] = t.x; ql_[ks][3] = t.y;
    }

    asm volatile("cp.async.wait_group 2;\n" ::: "memory");  // k done
    __syncthreads();

    // logits(log2) = q @ k^T
    float acc[8][4];
#pragma unroll
    for (int a = 0; a < 8; a++)
#pragma unroll
        for (int c = 0; c < 4; c++) acc[a][c] = 0.f;

#pragma unroll
    for (int ks = 0; ks < 2; ks++) {
        int j0 = ks * 8;
#pragma unroll
        for (int nfp = 0; nfp < 4; nfp++) {
            int nf0 = 2 * nfp, nf1 = nf0 + 1;
            int n0 = nf0 * 8 + g;
            uint2 c0 = k2s[n0][j0 + tg],     c1 = k2s[n0][j0 + tg + 4];
            uint2 d0 = k2s[n0 + 8][j0 + tg], d1 = k2s[n0 + 8][j0 + tg + 4];
            mma_bf16(acc[nf0], qh_[ks], c0.x, c1.x);
            mma_bf16(acc[nf1], qh_[ks], d0.x, d1.x);
            mma_bf16(acc[nf0], qh_[ks], c0.y, c1.y);
            mma_bf16(acc[nf1], qh_[ks], d0.y, d1.y);
            mma_bf16(acc[nf0], ql_[ks], c0.x, c1.x);
            mma_bf16(acc[nf1], ql_[ks], d0.x, d1.x);
        }
    }

    // wait v + bm, full barrier (v is cross-warp)
    asm volatile("cp.async.wait_group 0;\n" ::: "memory");
    __syncthreads();

    int r0 = mr + g, r1 = r0 + 8;
#pragma unroll
    for (int nf = 0; nf < 8; nf++) {
        int n0 = nf * 8 + 2 * tg;
        float2 e0 = *(const float2*)(&bms[r0][n0]);
        float2 e1 = *(const float2*)(&bms[r1][n0]);
        acc[nf][0] += e0.x; acc[nf][1] += e0.y;
        acc[nf][2] += e1.x; acc[nf][3] += e1.y;
    }

    // softmax (log2 domain) across the quad (rows r0, r1)
    float m0 = -1e30f, m1 = -1e30f;
#pragma unroll
    for (int nf = 0; nf < 8; nf++) {
        m0 = fmaxf(m0, fmaxf(acc[nf][0], acc[nf][1]));
        m1 = fmaxf(m1, fmaxf(acc[nf][2], acc[nf][3]));
    }
    m0 = fmaxf(m0, __shfl_xor_sync(0xffffffffu, m0, 1));
    m0 = fmaxf(m0, __shfl_xor_sync(0xffffffffu, m0, 2));
    m1 = fmaxf(m1, __shfl_xor_sync(0xffffffffu, m1, 1));
    m1 = fmaxf(m1, __shfl_xor_sync(0xffffffffu, m1, 2));

    float s0 = 0.f, s1 = 0.f;
#pragma unroll
    for (int nf = 0; nf < 8; nf++) {
        acc[nf][0] = ex2(acc[nf][0] - m0); s0 += acc[nf][0];
        acc[nf][1] = ex2(acc[nf][1] - m0); s0 += acc[nf][1];
        acc[nf][2] = ex2(acc[nf][2] - m1); s1 += acc[nf][2];
        acc[nf][3] = ex2(acc[nf][3] - m1); s1 += acc[nf][3];
    }
    s0 += __shfl_xor_sync(0xffffffffu, s0, 1);
    s0 += __shfl_xor_sync(0xffffffffu, s0, 2);
    s1 += __shfl_xor_sync(0xffffffffu, s1, 1);
    s1 += __shfl_xor_sync(0xffffffffu, s1, 2);
    float i0 = 1.f / s0, i1 = 1.f / s1;

    // out = P @ V — P a-frags from acc (lane-local), V b-frags via ldsm.trans
    float oacc[4][4];
#pragma unroll
    for (int a = 0; a < 4; a++)
#pragma unroll
        for (int c = 0; c < 4; c++) oacc[a][c] = 0.f;

    uint32_t vrow = (uint32_t)(((lane >> 3) & 1) * 8 + (lane & 7));
    uint32_t vcol = (uint32_t)((lane >> 4) * 16);
    uint32_t vh_l = vhb + vrow * 80 + vcol;
    uint32_t vl_l = vlb + vrow * 80 + vcol;

#pragma unroll
    for (int ks = 0; ks < 4; ks++) {
        uint32_t ah[4], al[4];
        split2(acc[2 * ks][0] * i0,     acc[2 * ks][1] * i0,     ah[0], al[0]);
        split2(acc[2 * ks][2] * i1,     acc[2 * ks][3] * i1,     ah[1], al[1]);
        split2(acc[2 * ks + 1][0] * i0, acc[2 * ks + 1][1] * i0, ah[2], al[2]);
        split2(acc[2 * ks + 1][2] * i1, acc[2 * ks + 1][3] * i1, ah[3], al[3]);
        uint32_t ko = (uint32_t)(ks * 16 * 80);
        uint32_t bh0[4], bh1[4], bl0[4], bl1[4];
        ldsm4t(bh0, vh_l + ko);        // d 0-15  (b0,b1 for d0-7; d8-15)
        ldsm4t(bh1, vh_l + ko + 32);   // d 16-31
        ldsm4t(bl0, vl_l + ko);
        ldsm4t(bl1, vl_l + ko + 32);
        mma_bf16(oacc[0], ah, bh0[0], bh0[1]);
        mma_bf16(oacc[1], ah, bh0[2], bh0[3]);
        mma_bf16(oacc[2], ah, bh1[0], bh1[1]);
        mma_bf16(oacc[3], ah, bh1[2], bh1[3]);
        mma_bf16(oacc[0], ah, bl0[0], bl0[1]);
        mma_bf16(oacc[1], ah, bl0[2], bl0[3]);
        mma_bf16(oacc[2], ah, bl1[0], bl1[1]);
        mma_bf16(oacc[3], ah, bl1[2], bl1[3]);
        mma_bf16(oacc[0], al, bh0[0], bh0[1]);
        mma_bf16(oacc[1], al, bh0[2], bh0[3]);
        mma_bf16(oacc[2], al, bh1[0], bh1[1]);
        mma_bf16(oacc[3], al, bh1[2], bh1[3]);
    }

    // ctx -> proj operand planes
    int m0r = b * 64 + r0, m1r = b * 64 + r1;
#pragma unroll
    for (int nf = 0; nf < 4; nf++) {
        int dp = h * 16 + nf * 4 + tg;
        int kb = dp >> 4, q = dp & 15;
        uint32_t hi, lo;
        {
            size_t idx = ((size_t)((m0r >> 7) * 8 + kb)) * 2048 + plane_pair(m0r & 127, q);
            split2(oacc[nf][0], oacc[nf][1], hi, lo);
            g_othi[idx] = hi; g_otlo[idx] = lo;
        }
        {
            size_t idx = ((size_t)((m1r >> 7) * 8 + kb)) * 2048 + plane_pair(m1r & 127, q);
            split2(oacc[nf][2], oacc[nf][3], hi, lo);
            g_othi[idx] = hi; g_otlo[idx] = lo;
        }
    }
}

// ---------------------------------------------------------------------------
extern "C" void kernel_launch(void* const* d_in, const int* in_sizes, int n_in,
                              void* d_out, int out_size) {
    (void)in_sizes; (void)n_in; (void)out_size;
    const float* x       = (const float*)d_in[0];
    const float* mask    = (const float*)d_in[1];
    const float* qkv_w   = (const float*)d_in[2];
    const float* qkv_b   = (const float*)d_in[3];
    const float* proj_w  = (const float*)d_in[4];
    const float* proj_b  = (const float*)d_in[5];
    const float* pposw   = (const float*)d_in[6];
    const float* pposb   = (const float*)d_in[7];
    const float* ln1g    = (const float*)d_in[8];
    const float* ln1b    = (const float*)d_in[9];
    const float* fc1w    = (const float*)d_in[10];
    const float* fc1b    = (const float*)d_in[11];
    const float* ln2g    = (const float*)d_in[12];
    const float* ln2b    = (const float*)d_in[13];
    const float* fc2w    = (const float*)d_in[14];
    const float* fc2b    = (const float*)d_in[15];
    const float* ln3g    = (const float*)d_in[16];
    const float* ln3b    = (const float*)d_in[17];
    const float* fc3w    = (const float*)d_in[18];
    const float* fc3b    = (const float*)d_in[19];
    const float* biases  = (const float*)d_in[20];
    const int*   rel_idx = (const int*)d_in[21];
    float* out = (float*)d_out;

    static bool attr_set = false;
    if (!attr_set) {
        cudaFuncSetAttribute(gemm_kernel<0>, cudaFuncAttributeMaxDynamicSharedMemorySize, 98304);
        cudaFuncSetAttribute(gemm_kernel<1>, cudaFuncAttributeMaxDynamicSharedMemorySize, 98304);
        attr_set = true;
    }

    dpb_kernel<<<1, 256>>>(biases, pposw, pposb, ln1g, ln1b, fc1w, fc1b,
                           ln2g, ln2b, fc2w, fc2b, ln3g, ln3b, fc3w, fc3b);
    presplit_kernel<<<50432, 256>>>(x, qkv_w, proj_w);
    bmtab_kernel<<<dim3(NW, HEADS), 256>>>(mask, rel_idx);
    gemm_kernel<0><<<dim3(6, 1568), 256, 98304>>>(qkv_b, nullptr);
    attn_kernel<<<dim3(B_WIN, HEADS), 128>>>();
    gemm_kernel<1><<<dim3(2, 1568), 256, 98304>>>(proj_b, out);
}